// round 5
// baseline (speedup 1.0000x reference)
#include <cuda_runtime.h>
#include <cuda_bf16.h>
#include <cstdint>

// ============================================================================
// ConvolutionFromEdgeSetUpdate:
//   messages = relu([node[src] | node[tgt] | edge] @ W + b)   (E x 64)
//   out      = segment_sum(messages, tgt, 50000)
// E=800000, D=64, U=64, K=192.
//
// R5 = R2 (373us baseline) with EXACTLY ONE change: coalesced gather
// (16 threads x 16B per row instead of thread-per-row), which removes ~5k
// L1 wavefront-cycles per tile. Warp tile, MMA inner loop, epilogue, and
// barrier structure are IDENTICAL to R2.
// ============================================================================

#define NN_NODES 50000
#define NN_EDGES 800000
#define D_FEAT   64
#define UNITS    64
#define KDIM     192
#define TILE_M   128
#define N_TILES  (NN_EDGES / TILE_M)   // 6250
#define THREADS  256                   // 8 warps; each warp owns 16 rows
#define GRID_X   148

// SMEM: row-major bf16 tiles, row stride 200 bf16 = 400 B (16B-aligned, and
// 400 mod 128 = 16 so ldmatrix row sets are bank-conflict-free).
#define STRIDE_B   400
#define SM_A_HI    0
#define SM_A_LO    (SM_A_HI + TILE_M * STRIDE_B)     // 51200
#define SM_B_HI    (SM_A_LO + TILE_M * STRIDE_B)     // 102400
#define SM_B_LO    (SM_B_HI + UNITS * STRIDE_B)      // 128000
#define SM_TOTAL   (SM_B_LO + UNITS * STRIDE_B)      // 153600

// ---------------- helpers ----------------

__device__ __forceinline__ uint32_t smem_to_u32(const void* smem_ptr) {
    uint32_t addr;
    asm("{ .reg .u64 tmp; cvta.to.shared.u64 tmp, %1; cvt.u32.u64 %0, tmp; }"
        : "=r"(addr) : "l"(smem_ptr));
    return addr;
}

__device__ __forceinline__ void ldsm_x4(uint32_t* r, uint32_t addr) {
    asm volatile("ldmatrix.sync.aligned.m8n8.x4.shared.b16 {%0,%1,%2,%3}, [%4];"
        : "=r"(r[0]), "=r"(r[1]), "=r"(r[2]), "=r"(r[3]) : "r"(addr));
}

__device__ __forceinline__ void ldsm_x2(uint32_t* r, uint32_t addr) {
    asm volatile("ldmatrix.sync.aligned.m8n8.x2.shared.b16 {%0,%1}, [%2];"
        : "=r"(r[0]), "=r"(r[1]) : "r"(addr));
}

__device__ __forceinline__ void mma_bf16(float* c, const uint32_t* a, const uint32_t* b) {
    asm volatile(
        "mma.sync.aligned.m16n8k16.row.col.f32.bf16.bf16.f32 "
        "{%0,%1,%2,%3}, {%4,%5,%6,%7}, {%8,%9}, {%0,%1,%2,%3};"
        : "+f"(c[0]), "+f"(c[1]), "+f"(c[2]), "+f"(c[3])
        : "r"(a[0]), "r"(a[1]), "r"(a[2]), "r"(a[3]), "r"(b[0]), "r"(b[1]));
}

__device__ __forceinline__ uint32_t pack_bf16x2(float a, float b) {
    __nv_bfloat162 t = __halves2bfloat162(__float2bfloat16(a), __float2bfloat16(b));
    return *reinterpret_cast<uint32_t*>(&t);
}

__device__ __forceinline__ void split2(float x, float& hi_f, float& lo_f) {
    __nv_bfloat16 h = __float2bfloat16(x);
    hi_f = __bfloat162float(h);
    lo_f = x - hi_f;
}

// ---------------- zero output (d_out is poisoned 0xAA) ----------------

__global__ void zero_out_kernel(float4* out) {
    int i = blockIdx.x * blockDim.x + threadIdx.x;
    if (i < NN_NODES * UNITS / 4) out[i] = make_float4(0.f, 0.f, 0.f, 0.f);
}

// ---------------- main fused kernel ----------------

__global__ __launch_bounds__(THREADS, 1)
void edgeconv_kernel(const float* __restrict__ node_feat,
                     const float* __restrict__ edge_feat,
                     const int*   __restrict__ src_idx,
                     const int*   __restrict__ tgt_idx,
                     const float* __restrict__ W,
                     const float* __restrict__ bias,
                     float*       __restrict__ out)
{
    extern __shared__ char smem[];
    const uint32_t smem_base = smem_to_u32(smem);
    const int tid  = threadIdx.x;
    const int wid  = tid >> 5;
    const int lane = tid & 31;

    // ---- build B = W^T hi/lo in SMEM: Bsm[n][k], n rows, k contiguous ----
    for (int task = tid; task < 192; task += THREADS) {
        const int n = task & 63, bseg = task >> 6;
        char* rowp_hi = smem + SM_B_HI + n * STRIDE_B;
        char* rowp_lo = smem + SM_B_LO + n * STRIDE_B;
        #pragma unroll 8
        for (int j = 0; j < 64; ++j) {
            const int k = bseg * 64 + j;
            float x = W[k * UNITS + n];
            float hf, lf; split2(x, hf, lf);
            *reinterpret_cast<__nv_bfloat16*>(rowp_hi + k * 2) = __float2bfloat16(hf);
            *reinterpret_cast<__nv_bfloat16*>(rowp_lo + k * 2) = __float2bfloat16(lf);
        }
    }

    // per-thread bias for epilogue: cols j*8 + 2*(lane&3) + {0,1}
    const int t4 = lane & 3;
    const int g  = lane >> 2;
    float bj0[8], bj1[8];
    #pragma unroll
    for (int j = 0; j < 8; ++j) {
        bj0[j] = bias[j * 8 + 2 * t4];
        bj1[j] = bias[j * 8 + 2 * t4 + 1];
    }

    // ldmatrix per-lane address components (byte offsets)
    const uint32_t a_lane_off =
        (uint32_t)((wid * 16 + (lane & 15)) * STRIDE_B + (lane >> 4) * 16);
    const uint32_t b_lane_off =
        (uint32_t)((lane & 7) * STRIDE_B + ((lane >> 3) & 1) * 16);

    const uint32_t aHI = smem_base + SM_A_HI + a_lane_off;
    const uint32_t aLO = smem_base + SM_A_LO + a_lane_off;
    const uint32_t bHI = smem_base + SM_B_HI + b_lane_off;
    const uint32_t bLO = smem_base + SM_B_LO + b_lane_off;

    // coalesced gather mapping: 16 threads per (row,seg), one 16B chunk each
    const int g_chunk = tid & 15;          // float4 index within 64-float row
    const int g_rs0   = tid >> 4;          // first rowseg (0..15), step 16

    __syncthreads();   // B tiles ready

    for (int tile = blockIdx.x; tile < N_TILES; tile += GRID_X) {
        // ============ gather + convert A tile (hi/lo), coalesced ============
        // rowsegs: 0..127 src rows, 128..255 tgt rows, 256..383 edge rows
        #pragma unroll 4
        for (int rs = g_rs0; rs < 3 * TILE_M; rs += THREADS / 16) {
            const int row = rs & (TILE_M - 1);
            const int seg = rs >> 7;               // 0,1,2
            const int e   = tile * TILE_M + row;
            const float* p;
            if (seg == 0)      p = node_feat + (size_t)__ldg(src_idx + e) * D_FEAT;
            else if (seg == 1) p = node_feat + (size_t)__ldg(tgt_idx + e) * D_FEAT;
            else               p = edge_feat + (size_t)e * D_FEAT;
            float4 v = __ldg(reinterpret_cast<const float4*>(p) + g_chunk);
            float h0,l0,h1,l1,h2,l2,h3,l3;
            split2(v.x, h0, l0); split2(v.y, h1, l1);
            split2(v.z, h2, l2); split2(v.w, h3, l3);
            uint2 hh; hh.x = pack_bf16x2(h0, h1); hh.y = pack_bf16x2(h2, h3);
            uint2 ll; ll.x = pack_bf16x2(l0, l1); ll.y = pack_bf16x2(l2, l3);
            const uint32_t off = (uint32_t)(row * STRIDE_B + seg * 128 + g_chunk * 8);
            *reinterpret_cast<uint2*>(smem + SM_A_HI + off) = hh;
            *reinterpret_cast<uint2*>(smem + SM_A_LO + off) = ll;
        }
        __syncthreads();

        // ============ MMA: 16 rows per warp, full N=64, K=192 (as R2) =======
        float acc[8][4];
        #pragma unroll
        for (int j = 0; j < 8; ++j) {
            acc[j][0] = 0.f; acc[j][1] = 0.f; acc[j][2] = 0.f; acc[j][3] = 0.f;
        }

        #pragma unroll
        for (int ks = 0; ks < KDIM / 16; ++ks) {   // 12 k-steps
            const uint32_t kb = (uint32_t)(ks * 32);
            uint32_t ahi[4], alo[4];
            ldsm_x4(ahi, aHI + kb);
            ldsm_x4(alo, aLO + kb);
            #pragma unroll
            for (int j = 0; j < 8; ++j) {
                uint32_t bhi[2], blo[2];
                const uint32_t bj = (uint32_t)(j * 8 * STRIDE_B) + kb;
                ldsm_x2(bhi, bHI + bj);
                ldsm_x2(blo, bLO + bj);
                mma_bf16(acc[j], ahi, bhi);
                mma_bf16(acc[j], ahi, blo);
                mma_bf16(acc[j], alo, bhi);
            }
        }
        __syncthreads();   // A tile free for next iteration's gather

        // ============ epilogue: bias + relu + red.v2 scatter (as R2) ========
        {
            const int e0 = tile * TILE_M + wid * 16 + g;
            const int e1 = e0 + 8;
            const int tgt0 = __ldg(tgt_idx + e0);
            const int tgt1 = __ldg(tgt_idx + e1);
            float* o0 = out + (size_t)tgt0 * UNITS + 2 * t4;
            float* o1 = out + (size_t)tgt1 * UNITS + 2 * t4;
            #pragma unroll
            for (int j = 0; j < 8; ++j) {
                float v0 = fmaxf(acc[j][0] + bj0[j], 0.f);
                float v1 = fmaxf(acc[j][1] + bj1[j], 0.f);
                float v2 = fmaxf(acc[j][2] + bj0[j], 0.f);
                float v3 = fmaxf(acc[j][3] + bj1[j], 0.f);
                asm volatile("red.global.add.v2.f32 [%0], {%1, %2};"
                             :: "l"(o0 + j * 8), "f"(v0), "f"(v1) : "memory");
                asm volatile("red.global.add.v2.f32 [%0], {%1, %2};"
                             :: "l"(o1 + j * 8), "f"(v2), "f"(v3) : "memory");
            }
        }
    }
}

// ---------------- launch ----------------

extern "C" void kernel_launch(void* const* d_in, const int* in_sizes, int n_in,
                              void* d_out, int out_size) {
    const float* node_feat = (const float*)d_in[0];
    const float* edge_feat = (const float*)d_in[1];
    const int*   src_idx   = (const int*)d_in[2];
    const int*   tgt_idx   = (const int*)d_in[3];
    const float* W         = (const float*)d_in[4];
    const float* b         = (const float*)d_in[5];
    float* out = (float*)d_out;

    int n4 = NN_NODES * UNITS / 4;
    zero_out_kernel<<<(n4 + 255) / 256, 256>>>((float4*)out);

    static int configured = 0;
    if (!configured) {
        cudaFuncSetAttribute(edgeconv_kernel,
                             cudaFuncAttributeMaxDynamicSharedMemorySize, SM_TOTAL);
        configured = 1;
    }
    edgeconv_kernel<<<GRID_X, THREADS, SM_TOTAL>>>(
        node_feat, edge_feat, src_idx, tgt_idx, W, b, out);
}

// round 6
// speedup vs baseline: 1.9615x; 1.9615x over previous
#include <cuda_runtime.h>
#include <cuda_bf16.h>
#include <cstdint>

// ============================================================================
// ConvolutionFromEdgeSetUpdate:
//   messages = relu([node[src] | node[tgt] | edge] @ W + b)   (E x 64)
//   out      = segment_sum(messages, tgt, 50000)
// E=800000, D=64, U=64, K=192.
//
// R6 = R2 (373us best) with ONE structural change: 512 threads (16 warps/SM)
// instead of 256, warp tile 16x32 (8 m-groups x 2 n-groups). Total ldsm/STS/
// LDG work per tile is IDENTICAL to R2; the extra warps exist purely to hide
// latency (R3/R4/R5 all proved the kernel is latency-bound at 8 warps/SM).
// Gather is R2's exact thread-per-row high-MLP form.
// ============================================================================

#define NN_NODES 50000
#define NN_EDGES 800000
#define D_FEAT   64
#define UNITS    64
#define KDIM     192
#define TILE_M   128
#define N_TILES  (NN_EDGES / TILE_M)   // 6250
#define THREADS  512                   // 16 warps: 8 m-groups x 2 n-groups
#define GRID_X   148

// SMEM: row-major bf16 tiles, row stride 200 bf16 = 400 B (16B-aligned, and
// 400 mod 128 = 16 so ldmatrix row sets are bank-conflict-free).
#define STRIDE_B   400
#define SM_A_HI    0
#define SM_A_LO    (SM_A_HI + TILE_M * STRIDE_B)     // 51200
#define SM_B_HI    (SM_A_LO + TILE_M * STRIDE_B)     // 102400
#define SM_B_LO    (SM_B_HI + UNITS * STRIDE_B)      // 128000
#define SM_TOTAL   (SM_B_LO + UNITS * STRIDE_B)      // 153600

// ---------------- helpers ----------------

__device__ __forceinline__ uint32_t smem_to_u32(const void* smem_ptr) {
    uint32_t addr;
    asm("{ .reg .u64 tmp; cvta.to.shared.u64 tmp, %1; cvt.u32.u64 %0, tmp; }"
        : "=r"(addr) : "l"(smem_ptr));
    return addr;
}

__device__ __forceinline__ void ldsm_x4(uint32_t* r, uint32_t addr) {
    asm volatile("ldmatrix.sync.aligned.m8n8.x4.shared.b16 {%0,%1,%2,%3}, [%4];"
        : "=r"(r[0]), "=r"(r[1]), "=r"(r[2]), "=r"(r[3]) : "r"(addr));
}

__device__ __forceinline__ void ldsm_x2(uint32_t* r, uint32_t addr) {
    asm volatile("ldmatrix.sync.aligned.m8n8.x2.shared.b16 {%0,%1}, [%2];"
        : "=r"(r[0]), "=r"(r[1]) : "r"(addr));
}

__device__ __forceinline__ void mma_bf16(float* c, const uint32_t* a, const uint32_t* b) {
    asm volatile(
        "mma.sync.aligned.m16n8k16.row.col.f32.bf16.bf16.f32 "
        "{%0,%1,%2,%3}, {%4,%5,%6,%7}, {%8,%9}, {%0,%1,%2,%3};"
        : "+f"(c[0]), "+f"(c[1]), "+f"(c[2]), "+f"(c[3])
        : "r"(a[0]), "r"(a[1]), "r"(a[2]), "r"(a[3]), "r"(b[0]), "r"(b[1]));
}

__device__ __forceinline__ uint32_t pack_bf16x2(float a, float b) {
    __nv_bfloat162 t = __halves2bfloat162(__float2bfloat16(a), __float2bfloat16(b));
    return *reinterpret_cast<uint32_t*>(&t);
}

__device__ __forceinline__ void split2(float x, float& hi_f, float& lo_f) {
    __nv_bfloat16 h = __float2bfloat16(x);
    hi_f = __bfloat162float(h);
    lo_f = x - hi_f;
}

// ---------------- zero output (d_out is poisoned 0xAA) ----------------

__global__ void zero_out_kernel(float4* out) {
    int i = blockIdx.x * blockDim.x + threadIdx.x;
    if (i < NN_NODES * UNITS / 4) out[i] = make_float4(0.f, 0.f, 0.f, 0.f);
}

// ---------------- main fused kernel ----------------

__global__ __launch_bounds__(THREADS, 1)
void edgeconv_kernel(const float* __restrict__ node_feat,
                     const float* __restrict__ edge_feat,
                     const int*   __restrict__ src_idx,
                     const int*   __restrict__ tgt_idx,
                     const float* __restrict__ W,
                     const float* __restrict__ bias,
                     float*       __restrict__ out)
{
    extern __shared__ char smem[];
    const uint32_t smem_base = smem_to_u32(smem);
    const int tid  = threadIdx.x;
    const int wid  = tid >> 5;
    const int lane = tid & 31;

    // ---- build B = W^T hi/lo in SMEM: Bsm[n][k], n rows, k contiguous ----
    for (int task = tid; task < 192; task += THREADS) {
        const int n = task & 63, bseg = task >> 6;
        char* rowp_hi = smem + SM_B_HI + n * STRIDE_B;
        char* rowp_lo = smem + SM_B_LO + n * STRIDE_B;
        #pragma unroll 8
        for (int j = 0; j < 64; ++j) {
            const int k = bseg * 64 + j;
            float x = W[k * UNITS + n];
            float hf, lf; split2(x, hf, lf);
            *reinterpret_cast<__nv_bfloat16*>(rowp_hi + k * 2) = __float2bfloat16(hf);
            *reinterpret_cast<__nv_bfloat16*>(rowp_lo + k * 2) = __float2bfloat16(lf);
        }
    }

    // warp tile: mg in {0..7} picks 16 rows, ng in {0,1} picks 32 cols
    const int mg = wid >> 1;
    const int ng = wid & 1;
    const int t4 = lane & 3;
    const int g  = lane >> 2;

    // per-thread bias for epilogue: cols ng*32 + j*8 + 2*t4 + {0,1}
    float bj0[4], bj1[4];
    #pragma unroll
    for (int j = 0; j < 4; ++j) {
        bj0[j] = bias[ng * 32 + j * 8 + 2 * t4];
        bj1[j] = bias[ng * 32 + j * 8 + 2 * t4 + 1];
    }

    // ldmatrix per-lane address components (byte offsets)
    const uint32_t a_lane_off =
        (uint32_t)((mg * 16 + (lane & 15)) * STRIDE_B + (lane >> 4) * 16);
    const uint32_t b_lane_off =
        (uint32_t)((ng * 32 + (lane & 7)) * STRIDE_B + ((lane >> 3) & 1) * 16);

    const uint32_t aHI = smem_base + SM_A_HI + a_lane_off;
    const uint32_t aLO = smem_base + SM_A_LO + a_lane_off;
    const uint32_t bHI = smem_base + SM_B_HI + b_lane_off;
    const uint32_t bLO = smem_base + SM_B_LO + b_lane_off;

    __syncthreads();   // B tiles ready

    for (int tile = blockIdx.x; tile < N_TILES; tile += GRID_X) {
        // ============ gather + convert A tile (hi/lo) — R2's exact form =====
        // 384 tasks: row in [0,128), seg in {src, tgt, edge}; thread-per-row,
        // 16 independent 16B loads per thread (high MLP).
        if (tid < 3 * TILE_M) {
            const int row = tid & (TILE_M - 1);
            const int seg = tid >> 7;              // 0,1,2
            const int e   = tile * TILE_M + row;
            const float* p;
            if (seg == 0)      p = node_feat + (size_t)__ldg(src_idx + e) * D_FEAT;
            else if (seg == 1) p = node_feat + (size_t)__ldg(tgt_idx + e) * D_FEAT;
            else               p = edge_feat + (size_t)e * D_FEAT;
            const float4* p4 = reinterpret_cast<const float4*>(p);
            char* dst_hi = smem + SM_A_HI + row * STRIDE_B + seg * 128;
            char* dst_lo = smem + SM_A_LO + row * STRIDE_B + seg * 128;
            #pragma unroll
            for (int q = 0; q < 8; ++q) {          // 8 x (8 floats -> 16B hi + 16B lo)
                float4 v0 = __ldg(p4 + 2 * q);
                float4 v1 = __ldg(p4 + 2 * q + 1);
                uint4 hh, ll;
                float h0,l0,h1,l1,h2,l2,h3,l3;
                split2(v0.x, h0, l0); split2(v0.y, h1, l1);
                split2(v0.z, h2, l2); split2(v0.w, h3, l3);
                hh.x = pack_bf16x2(h0, h1); hh.y = pack_bf16x2(h2, h3);
                ll.x = pack_bf16x2(l0, l1); ll.y = pack_bf16x2(l2, l3);
                split2(v1.x, h0, l0); split2(v1.y, h1, l1);
                split2(v1.z, h2, l2); split2(v1.w, h3, l3);
                hh.z = pack_bf16x2(h0, h1); hh.w = pack_bf16x2(h2, h3);
                ll.z = pack_bf16x2(l0, l1); ll.w = pack_bf16x2(l2, l3);
                *reinterpret_cast<uint4*>(dst_hi + q * 16) = hh;
                *reinterpret_cast<uint4*>(dst_lo + q * 16) = ll;
            }
        }
        __syncthreads();

        // ============ MMA: 16 rows x 32 cols per warp, K=192 ============
        float acc[4][4];
        #pragma unroll
        for (int j = 0; j < 4; ++j) {
            acc[j][0] = 0.f; acc[j][1] = 0.f; acc[j][2] = 0.f; acc[j][3] = 0.f;
        }

        #pragma unroll
        for (int ks = 0; ks < KDIM / 16; ++ks) {   // 12 k-steps
            const uint32_t kb = (uint32_t)(ks * 32);
            uint32_t ahi[4], alo[4];
            ldsm_x4(ahi, aHI + kb);
            ldsm_x4(alo, aLO + kb);
            #pragma unroll
            for (int j = 0; j < 4; ++j) {
                uint32_t bhi[2], blo[2];
                const uint32_t bj = (uint32_t)(j * 8 * STRIDE_B) + kb;
                ldsm_x2(bhi, bHI + bj);
                ldsm_x2(blo, bLO + bj);
                mma_bf16(acc[j], ahi, bhi);
                mma_bf16(acc[j], ahi, blo);
                mma_bf16(acc[j], alo, bhi);
            }
        }
        __syncthreads();   // A tile free for next iteration's gather

        // ============ epilogue: bias + relu + red.v2 scatter ============
        {
            const int e0 = tile * TILE_M + mg * 16 + g;
            const int e1 = e0 + 8;
            const int tgt0 = __ldg(tgt_idx + e0);
            const int tgt1 = __ldg(tgt_idx + e1);
            float* o0 = out + (size_t)tgt0 * UNITS + ng * 32 + 2 * t4;
            float* o1 = out + (size_t)tgt1 * UNITS + ng * 32 + 2 * t4;
            #pragma unroll
            for (int j = 0; j < 4; ++j) {
                float v0 = fmaxf(acc[j][0] + bj0[j], 0.f);
                float v1 = fmaxf(acc[j][1] + bj1[j], 0.f);
                float v2 = fmaxf(acc[j][2] + bj0[j], 0.f);
                float v3 = fmaxf(acc[j][3] + bj1[j], 0.f);
                asm volatile("red.global.add.v2.f32 [%0], {%1, %2};"
                             :: "l"(o0 + j * 8), "f"(v0), "f"(v1) : "memory");
                asm volatile("red.global.add.v2.f32 [%0], {%1, %2};"
                             :: "l"(o1 + j * 8), "f"(v2), "f"(v3) : "memory");
            }
        }
    }
}

// ---------------- launch ----------------

extern "C" void kernel_launch(void* const* d_in, const int* in_sizes, int n_in,
                              void* d_out, int out_size) {
    const float* node_feat = (const float*)d_in[0];
    const float* edge_feat = (const float*)d_in[1];
    const int*   src_idx   = (const int*)d_in[2];
    const int*   tgt_idx   = (const int*)d_in[3];
    const float* W         = (const float*)d_in[4];
    const float* b         = (const float*)d_in[5];
    float* out = (float*)d_out;

    int n4 = NN_NODES * UNITS / 4;
    zero_out_kernel<<<(n4 + 255) / 256, 256>>>((float4*)out);

    static int configured = 0;
    if (!configured) {
        cudaFuncSetAttribute(edgeconv_kernel,
                             cudaFuncAttributeMaxDynamicSharedMemorySize, SM_TOTAL);
        configured = 1;
    }
    edgeconv_kernel<<<GRID_X, THREADS, SM_TOTAL>>>(
        node_feat, edge_feat, src_idx, tgt_idx, W, b, out);
}

// round 7
// speedup vs baseline: 2.9019x; 1.4794x over previous
#include <cuda_runtime.h>
#include <cuda_bf16.h>
#include <cstdint>

// ============================================================================
// ConvolutionFromEdgeSetUpdate:
//   messages = relu([node[src] | node[tgt] | edge] @ W + b)   (E x 64)
//   out      = segment_sum(messages, tgt, 50000)
// E=800000, D=64, U=64, K=192.
//
// R7 = R6 (366us best: 512 thr, 16 warps, 16x32 warp tile, R2 MMA loop)
// with ONE change: the gather is coalesced (16 thr x 16B per row -> 4 lines
// per warp-LDG instead of 32) while keeping MLP via SMEM-staged indices
// (double-buffered, staged under the previous MMA phase) and feature loads
// issued in independent batches of 6.
// ============================================================================

#define NN_NODES 50000
#define NN_EDGES 800000
#define D_FEAT   64
#define UNITS    64
#define KDIM     192
#define TILE_M   128
#define N_TILES  (NN_EDGES / TILE_M)   // 6250
#define THREADS  512                   // 16 warps: 8 m-groups x 2 n-groups
#define GRID_X   148

// SMEM: row-major bf16 tiles, row stride 200 bf16 = 400 B (16B-aligned, and
// 400 mod 128 = 16 so ldmatrix row sets are bank-conflict-free).
#define STRIDE_B   400
#define SM_A_HI    0
#define SM_A_LO    (SM_A_HI + TILE_M * STRIDE_B)     // 51200
#define SM_B_HI    (SM_A_LO + TILE_M * STRIDE_B)     // 102400
#define SM_B_LO    (SM_B_HI + UNITS * STRIDE_B)      // 128000
#define SM_IDX     (SM_B_LO + UNITS * STRIDE_B)      // 153600: 2 bufs x 256 int
#define SM_TOTAL   (SM_IDX + 2 * 256 * 4)            // 155648

// ---------------- helpers ----------------

__device__ __forceinline__ uint32_t smem_to_u32(const void* smem_ptr) {
    uint32_t addr;
    asm("{ .reg .u64 tmp; cvta.to.shared.u64 tmp, %1; cvt.u32.u64 %0, tmp; }"
        : "=r"(addr) : "l"(smem_ptr));
    return addr;
}

__device__ __forceinline__ void ldsm_x4(uint32_t* r, uint32_t addr) {
    asm volatile("ldmatrix.sync.aligned.m8n8.x4.shared.b16 {%0,%1,%2,%3}, [%4];"
        : "=r"(r[0]), "=r"(r[1]), "=r"(r[2]), "=r"(r[3]) : "r"(addr));
}

__device__ __forceinline__ void ldsm_x2(uint32_t* r, uint32_t addr) {
    asm volatile("ldmatrix.sync.aligned.m8n8.x2.shared.b16 {%0,%1}, [%2];"
        : "=r"(r[0]), "=r"(r[1]) : "r"(addr));
}

__device__ __forceinline__ void mma_bf16(float* c, const uint32_t* a, const uint32_t* b) {
    asm volatile(
        "mma.sync.aligned.m16n8k16.row.col.f32.bf16.bf16.f32 "
        "{%0,%1,%2,%3}, {%4,%5,%6,%7}, {%8,%9}, {%0,%1,%2,%3};"
        : "+f"(c[0]), "+f"(c[1]), "+f"(c[2]), "+f"(c[3])
        : "r"(a[0]), "r"(a[1]), "r"(a[2]), "r"(a[3]), "r"(b[0]), "r"(b[1]));
}

__device__ __forceinline__ uint32_t pack_bf16x2(float a, float b) {
    __nv_bfloat162 t = __halves2bfloat162(__float2bfloat16(a), __float2bfloat16(b));
    return *reinterpret_cast<uint32_t*>(&t);
}

__device__ __forceinline__ void split2(float x, float& hi_f, float& lo_f) {
    __nv_bfloat16 h = __float2bfloat16(x);
    hi_f = __bfloat162float(h);
    lo_f = x - hi_f;
}

// ---------------- zero output (d_out is poisoned 0xAA) ----------------

__global__ void zero_out_kernel(float4* out) {
    int i = blockIdx.x * blockDim.x + threadIdx.x;
    if (i < NN_NODES * UNITS / 4) out[i] = make_float4(0.f, 0.f, 0.f, 0.f);
}

// ---------------- main fused kernel ----------------

__global__ __launch_bounds__(THREADS, 1)
void edgeconv_kernel(const float* __restrict__ node_feat,
                     const float* __restrict__ edge_feat,
                     const int*   __restrict__ src_idx,
                     const int*   __restrict__ tgt_idx,
                     const float* __restrict__ W,
                     const float* __restrict__ bias,
                     float*       __restrict__ out)
{
    extern __shared__ char smem[];
    const uint32_t smem_base = smem_to_u32(smem);
    const int tid  = threadIdx.x;
    const int wid  = tid >> 5;
    const int lane = tid & 31;

    int* const idx_sm = reinterpret_cast<int*>(smem + SM_IDX);

    // ---- build B = W^T hi/lo in SMEM: Bsm[n][k], n rows, k contiguous ----
    for (int task = tid; task < 192; task += THREADS) {
        const int n = task & 63, bseg = task >> 6;
        char* rowp_hi = smem + SM_B_HI + n * STRIDE_B;
        char* rowp_lo = smem + SM_B_LO + n * STRIDE_B;
        #pragma unroll 8
        for (int j = 0; j < 64; ++j) {
            const int k = bseg * 64 + j;
            float x = W[k * UNITS + n];
            float hf, lf; split2(x, hf, lf);
            *reinterpret_cast<__nv_bfloat16*>(rowp_hi + k * 2) = __float2bfloat16(hf);
            *reinterpret_cast<__nv_bfloat16*>(rowp_lo + k * 2) = __float2bfloat16(lf);
        }
    }

    // ---- stage indices for the first tile into buffer 0 ----
    if (tid < 256) {
        const int e = blockIdx.x * TILE_M + (tid & 127);
        idx_sm[tid] = (tid < 128) ? __ldg(src_idx + e) : __ldg(tgt_idx + e);
    }

    // warp tile: mg in {0..7} picks 16 rows, ng in {0,1} picks 32 cols
    const int mg = wid >> 1;
    const int ng = wid & 1;
    const int t4 = lane & 3;
    const int g  = lane >> 2;

    // per-thread bias for epilogue: cols ng*32 + j*8 + 2*t4 + {0,1}
    float bj0[4], bj1[4];
    #pragma unroll
    for (int j = 0; j < 4; ++j) {
        bj0[j] = bias[ng * 32 + j * 8 + 2 * t4];
        bj1[j] = bias[ng * 32 + j * 8 + 2 * t4 + 1];
    }

    // ldmatrix per-lane address components (byte offsets)
    const uint32_t a_lane_off =
        (uint32_t)((mg * 16 + (lane & 15)) * STRIDE_B + (lane >> 4) * 16);
    const uint32_t b_lane_off =
        (uint32_t)((ng * 32 + (lane & 7)) * STRIDE_B + ((lane >> 3) & 1) * 16);

    const uint32_t aHI = smem_base + SM_A_HI + a_lane_off;
    const uint32_t aLO = smem_base + SM_A_LO + a_lane_off;
    const uint32_t bHI = smem_base + SM_B_HI + b_lane_off;
    const uint32_t bLO = smem_base + SM_B_LO + b_lane_off;

    // coalesced gather mapping: 16 threads per (row,seg), one float4 each
    const int g_chunk = tid & 15;          // float4 index within 64-float row
    const int g_rs0   = tid >> 4;          // first rowseg (0..31), step 32

    __syncthreads();   // B tiles + idx buf0 ready

    int pb = 0;
    for (int tile = blockIdx.x; tile < N_TILES; tile += GRID_X) {
        const int* idxp = idx_sm + pb * 256;

        // ===== gather + convert A tile (hi/lo): coalesced, batched MLP =====
        // rowsegs: 0..127 src rows, 128..255 tgt rows, 256..383 edge rows.
        // 32 rowsegs per pass x 12 passes, grouped in 2 batches of 6
        // independent LDG.128s per thread.
        #pragma unroll
        for (int half = 0; half < 2; ++half) {
            const float* p[6];
            int rowv[6], segv[6];
            #pragma unroll
            for (int i = 0; i < 6; ++i) {
                const int rs  = g_rs0 + (half * 6 + i) * 32;
                const int row = rs & (TILE_M - 1);
                const int seg = rs >> 7;
                rowv[i] = row; segv[i] = seg;
                p[i] = (seg == 2)
                     ? edge_feat + (size_t)(tile * TILE_M + row) * D_FEAT
                     : node_feat + (size_t)idxp[rs] * D_FEAT;
            }
            float4 v[6];
            #pragma unroll
            for (int i = 0; i < 6; ++i)
                v[i] = __ldg(reinterpret_cast<const float4*>(p[i]) + g_chunk);
            #pragma unroll
            for (int i = 0; i < 6; ++i) {
                float h0,l0,h1,l1,h2,l2,h3,l3;
                split2(v[i].x, h0, l0); split2(v[i].y, h1, l1);
                split2(v[i].z, h2, l2); split2(v[i].w, h3, l3);
                uint2 hh; hh.x = pack_bf16x2(h0, h1); hh.y = pack_bf16x2(h2, h3);
                uint2 ll; ll.x = pack_bf16x2(l0, l1); ll.y = pack_bf16x2(l2, l3);
                const uint32_t off =
                    (uint32_t)(rowv[i] * STRIDE_B + segv[i] * 128 + g_chunk * 8);
                *reinterpret_cast<uint2*>(smem + SM_A_HI + off) = hh;
                *reinterpret_cast<uint2*>(smem + SM_A_LO + off) = ll;
            }
        }
        __syncthreads();

        // ---- stage next tile's indices (LDG latency hides under MMA) ----
        {
            const int nxt = tile + GRID_X;
            if (nxt < N_TILES && tid < 256) {
                const int e = nxt * TILE_M + (tid & 127);
                idx_sm[(pb ^ 1) * 256 + tid] =
                    (tid < 128) ? __ldg(src_idx + e) : __ldg(tgt_idx + e);
            }
        }

        // ============ MMA: 16 rows x 32 cols per warp, K=192 (as R6) ========
        float acc[4][4];
        #pragma unroll
        for (int j = 0; j < 4; ++j) {
            acc[j][0] = 0.f; acc[j][1] = 0.f; acc[j][2] = 0.f; acc[j][3] = 0.f;
        }

        #pragma unroll
        for (int ks = 0; ks < KDIM / 16; ++ks) {   // 12 k-steps
            const uint32_t kb = (uint32_t)(ks * 32);
            uint32_t ahi[4], alo[4];
            ldsm_x4(ahi, aHI + kb);
            ldsm_x4(alo, aLO + kb);
            #pragma unroll
            for (int j = 0; j < 4; ++j) {
                uint32_t bhi[2], blo[2];
                const uint32_t bj = (uint32_t)(j * 8 * STRIDE_B) + kb;
                ldsm_x2(bhi, bHI + bj);
                ldsm_x2(blo, bLO + bj);
                mma_bf16(acc[j], ahi, bhi);
                mma_bf16(acc[j], ahi, blo);
                mma_bf16(acc[j], alo, bhi);
            }
        }
        __syncthreads();   // A tile + idx bufs consistent for next iteration

        // ============ epilogue: bias + relu + red.v2 scatter (as R6) ========
        {
            const int r0 = mg * 16 + g;
            const int tgt0 = idxp[128 + r0];
            const int tgt1 = idxp[128 + r0 + 8];
            float* o0 = out + (size_t)tgt0 * UNITS + ng * 32 + 2 * t4;
            float* o1 = out + (size_t)tgt1 * UNITS + ng * 32 + 2 * t4;
            #pragma unroll
            for (int j = 0; j < 4; ++j) {
                float v0 = fmaxf(acc[j][0] + bj0[j], 0.f);
                float v1 = fmaxf(acc[j][1] + bj1[j], 0.f);
                float v2 = fmaxf(acc[j][2] + bj0[j], 0.f);
                float v3 = fmaxf(acc[j][3] + bj1[j], 0.f);
                asm volatile("red.global.add.v2.f32 [%0], {%1, %2};"
                             :: "l"(o0 + j * 8), "f"(v0), "f"(v1) : "memory");
                asm volatile("red.global.add.v2.f32 [%0], {%1, %2};"
                             :: "l"(o1 + j * 8), "f"(v2), "f"(v3) : "memory");
            }
        }
        pb ^= 1;
    }
}

// ---------------- launch ----------------

extern "C" void kernel_launch(void* const* d_in, const int* in_sizes, int n_in,
                              void* d_out, int out_size) {
    const float* node_feat = (const float*)d_in[0];
    const float* edge_feat = (const float*)d_in[1];
    const int*   src_idx   = (const int*)d_in[2];
    const int*   tgt_idx   = (const int*)d_in[3];
    const float* W         = (const float*)d_in[4];
    const float* b         = (const float*)d_in[5];
    float* out = (float*)d_out;

    int n4 = NN_NODES * UNITS / 4;
    zero_out_kernel<<<(n4 + 255) / 256, 256>>>((float4*)out);

    static int configured = 0;
    if (!configured) {
        cudaFuncSetAttribute(edgeconv_kernel,
                             cudaFuncAttributeMaxDynamicSharedMemorySize, SM_TOTAL);
        configured = 1;
    }
    edgeconv_kernel<<<GRID_X, THREADS, SM_TOTAL>>>(
        node_feat, edge_feat, src_idx, tgt_idx, W, b, out);
}

// round 8
// speedup vs baseline: 3.5635x; 1.2280x over previous
#include <cuda_runtime.h>
#include <cuda_fp16.h>
#include <cstdint>

// ============================================================================
// ConvolutionFromEdgeSetUpdate:
//   messages = relu([node[src] | node[tgt] | edge] @ W + b)   (E x 64)
//   out      = segment_sum(messages, tgt, 50000)
// E=800000, D=64, U=64, K=192.
//
// R8 = R7 (247us best) with the numeric engine swapped: fp16 2-product split.
//   A = Ahi + Alo (fp16 pair, ~21-bit precision); B single fp16 tile.
//   acc += Ahi*B + Alo*B  -> error = B fp16 quantization ~2.8e-4 RMS.
// Cuts ldsm traffic 590->392 KB/tile and HMMA count by 33% vs bf16 3-product.
// Skeleton (512 thr, 16x32 warp tile, batched-MLP coalesced gather, staged
// indices, red.v2 epilogue) is R7-verbatim.
// ============================================================================

#define NN_NODES 50000
#define NN_EDGES 800000
#define D_FEAT   64
#define UNITS    64
#define KDIM     192
#define TILE_M   128
#define N_TILES  (NN_EDGES / TILE_M)   // 6250
#define THREADS  512                   // 16 warps: 8 m-groups x 2 n-groups
#define GRID_X   148

// SMEM: row-major fp16 tiles, row stride 200 halves = 400 B (16B-aligned,
// 400 mod 128 = 16 -> ldmatrix row sets bank-conflict-free).
#define STRIDE_B   400
#define SM_A_HI    0
#define SM_A_LO    (SM_A_HI + TILE_M * STRIDE_B)     // 51200
#define SM_B       (SM_A_LO + TILE_M * STRIDE_B)     // 102400
#define SM_IDX     (SM_B + UNITS * STRIDE_B)         // 128000: 2 bufs x 256 int
#define SM_TOTAL   (SM_IDX + 2 * 256 * 4)            // 130048

// ---------------- helpers ----------------

__device__ __forceinline__ uint32_t smem_to_u32(const void* smem_ptr) {
    uint32_t addr;
    asm("{ .reg .u64 tmp; cvta.to.shared.u64 tmp, %1; cvt.u32.u64 %0, tmp; }"
        : "=r"(addr) : "l"(smem_ptr));
    return addr;
}

__device__ __forceinline__ void ldsm_x4(uint32_t* r, uint32_t addr) {
    asm volatile("ldmatrix.sync.aligned.m8n8.x4.shared.b16 {%0,%1,%2,%3}, [%4];"
        : "=r"(r[0]), "=r"(r[1]), "=r"(r[2]), "=r"(r[3]) : "r"(addr));
}

__device__ __forceinline__ void ldsm_x2(uint32_t* r, uint32_t addr) {
    asm volatile("ldmatrix.sync.aligned.m8n8.x2.shared.b16 {%0,%1}, [%2];"
        : "=r"(r[0]), "=r"(r[1]) : "r"(addr));
}

__device__ __forceinline__ void mma_f16(float* c, const uint32_t* a, const uint32_t* b) {
    asm volatile(
        "mma.sync.aligned.m16n8k16.row.col.f32.f16.f16.f32 "
        "{%0,%1,%2,%3}, {%4,%5,%6,%7}, {%8,%9}, {%0,%1,%2,%3};"
        : "+f"(c[0]), "+f"(c[1]), "+f"(c[2]), "+f"(c[3])
        : "r"(a[0]), "r"(a[1]), "r"(a[2]), "r"(a[3]), "r"(b[0]), "r"(b[1]));
}

__device__ __forceinline__ uint32_t pack_h2(__half a, __half b) {
    __half2 t = __halves2half2(a, b);
    return *reinterpret_cast<uint32_t*>(&t);
}

// split one float into fp16 hi + fp16 lo (residual)
__device__ __forceinline__ void split2h(float x, __half& h, __half& l) {
    h = __float2half_rn(x);
    l = __float2half_rn(x - __half2float(h));
}

// ---------------- zero output (d_out is poisoned 0xAA) ----------------

__global__ void zero_out_kernel(float4* out) {
    int i = blockIdx.x * blockDim.x + threadIdx.x;
    if (i < NN_NODES * UNITS / 4) out[i] = make_float4(0.f, 0.f, 0.f, 0.f);
}

// ---------------- main fused kernel ----------------

__global__ __launch_bounds__(THREADS, 1)
void edgeconv_kernel(const float* __restrict__ node_feat,
                     const float* __restrict__ edge_feat,
                     const int*   __restrict__ src_idx,
                     const int*   __restrict__ tgt_idx,
                     const float* __restrict__ W,
                     const float* __restrict__ bias,
                     float*       __restrict__ out)
{
    extern __shared__ char smem[];
    const uint32_t smem_base = smem_to_u32(smem);
    const int tid  = threadIdx.x;
    const int wid  = tid >> 5;
    const int lane = tid & 31;

    int* const idx_sm = reinterpret_cast<int*>(smem + SM_IDX);

    // ---- build B = W^T (single fp16) in SMEM: Bsm[n][k], k contiguous ----
    for (int task = tid; task < 192; task += THREADS) {
        const int n = task & 63, bseg = task >> 6;
        char* rowp = smem + SM_B + n * STRIDE_B;
        #pragma unroll 8
        for (int j = 0; j < 64; ++j) {
            const int k = bseg * 64 + j;
            *reinterpret_cast<__half*>(rowp + k * 2) = __float2half_rn(W[k * UNITS + n]);
        }
    }

    // ---- stage indices for the first tile into buffer 0 ----
    if (tid < 256) {
        const int e = blockIdx.x * TILE_M + (tid & 127);
        idx_sm[tid] = (tid < 128) ? __ldg(src_idx + e) : __ldg(tgt_idx + e);
    }

    // warp tile: mg in {0..7} picks 16 rows, ng in {0,1} picks 32 cols
    const int mg = wid >> 1;
    const int ng = wid & 1;
    const int t4 = lane & 3;
    const int g  = lane >> 2;

    // per-thread bias for epilogue: cols ng*32 + j*8 + 2*t4 + {0,1}
    float bj0[4], bj1[4];
    #pragma unroll
    for (int j = 0; j < 4; ++j) {
        bj0[j] = bias[ng * 32 + j * 8 + 2 * t4];
        bj1[j] = bias[ng * 32 + j * 8 + 2 * t4 + 1];
    }

    // ldmatrix per-lane address components (byte offsets)
    const uint32_t a_lane_off =
        (uint32_t)((mg * 16 + (lane & 15)) * STRIDE_B + (lane >> 4) * 16);
    const uint32_t b_lane_off =
        (uint32_t)((ng * 32 + (lane & 7)) * STRIDE_B + ((lane >> 3) & 1) * 16);

    const uint32_t aHI = smem_base + SM_A_HI + a_lane_off;
    const uint32_t aLO = smem_base + SM_A_LO + a_lane_off;
    const uint32_t bB  = smem_base + SM_B    + b_lane_off;

    // coalesced gather mapping: 16 threads per (row,seg), one float4 each
    const int g_chunk = tid & 15;          // float4 index within 64-float row
    const int g_rs0   = tid >> 4;          // first rowseg (0..31), step 32

    __syncthreads();   // B tile + idx buf0 ready

    int pb = 0;
    for (int tile = blockIdx.x; tile < N_TILES; tile += GRID_X) {
        const int* idxp = idx_sm + pb * 256;

        // ===== gather + convert A tile (hi/lo): coalesced, batched MLP =====
        // rowsegs: 0..127 src rows, 128..255 tgt rows, 256..383 edge rows.
        // 32 rowsegs per pass x 12 passes, 2 batches of 6 independent LDG.128.
        #pragma unroll
        for (int half = 0; half < 2; ++half) {
            const float* p[6];
            int rowv[6], segv[6];
            #pragma unroll
            for (int i = 0; i < 6; ++i) {
                const int rs  = g_rs0 + (half * 6 + i) * 32;
                const int row = rs & (TILE_M - 1);
                const int seg = rs >> 7;
                rowv[i] = row; segv[i] = seg;
                p[i] = (seg == 2)
                     ? edge_feat + (size_t)(tile * TILE_M + row) * D_FEAT
                     : node_feat + (size_t)idxp[rs] * D_FEAT;
            }
            float4 v[6];
            #pragma unroll
            for (int i = 0; i < 6; ++i)
                v[i] = __ldg(reinterpret_cast<const float4*>(p[i]) + g_chunk);
            #pragma unroll
            for (int i = 0; i < 6; ++i) {
                __half h0,l0,h1,l1,h2,l2,h3,l3;
                split2h(v[i].x, h0, l0); split2h(v[i].y, h1, l1);
                split2h(v[i].z, h2, l2); split2h(v[i].w, h3, l3);
                uint2 hh; hh.x = pack_h2(h0, h1); hh.y = pack_h2(h2, h3);
                uint2 ll; ll.x = pack_h2(l0, l1); ll.y = pack_h2(l2, l3);
                const uint32_t off =
                    (uint32_t)(rowv[i] * STRIDE_B + segv[i] * 128 + g_chunk * 8);
                *reinterpret_cast<uint2*>(smem + SM_A_HI + off) = hh;
                *reinterpret_cast<uint2*>(smem + SM_A_LO + off) = ll;
            }
        }
        __syncthreads();

        // ---- stage next tile's indices (LDG latency hides under MMA) ----
        {
            const int nxt = tile + GRID_X;
            if (nxt < N_TILES && tid < 256) {
                const int e = nxt * TILE_M + (tid & 127);
                idx_sm[(pb ^ 1) * 256 + tid] =
                    (tid < 128) ? __ldg(src_idx + e) : __ldg(tgt_idx + e);
            }
        }

        // ============ MMA: 16 rows x 32 cols per warp, K=192, 2 products ====
        float acc[4][4];
        #pragma unroll
        for (int j = 0; j < 4; ++j) {
            acc[j][0] = 0.f; acc[j][1] = 0.f; acc[j][2] = 0.f; acc[j][3] = 0.f;
        }

        #pragma unroll
        for (int ks = 0; ks < KDIM / 16; ++ks) {   // 12 k-steps
            const uint32_t kb = (uint32_t)(ks * 32);
            uint32_t ahi[4], alo[4];
            ldsm_x4(ahi, aHI + kb);
            ldsm_x4(alo, aLO + kb);
            #pragma unroll
            for (int j = 0; j < 4; ++j) {
                uint32_t bb[2];
                const uint32_t bj = (uint32_t)(j * 8 * STRIDE_B) + kb;
                ldsm_x2(bb, bB + bj);
                mma_f16(acc[j], ahi, bb);
                mma_f16(acc[j], alo, bb);
            }
        }
        __syncthreads();   // A tile + idx bufs consistent for next iteration

        // ============ epilogue: bias + relu + red.v2 scatter (as R7) ========
        {
            const int r0 = mg * 16 + g;
            const int tgt0 = idxp[128 + r0];
            const int tgt1 = idxp[128 + r0 + 8];
            float* o0 = out + (size_t)tgt0 * UNITS + ng * 32 + 2 * t4;
            float* o1 = out + (size_t)tgt1 * UNITS + ng * 32 + 2 * t4;
            #pragma unroll
            for (int j = 0; j < 4; ++j) {
                float v0 = fmaxf(acc[j][0] + bj0[j], 0.f);
                float v1 = fmaxf(acc[j][1] + bj1[j], 0.f);
                float v2 = fmaxf(acc[j][2] + bj0[j], 0.f);
                float v3 = fmaxf(acc[j][3] + bj1[j], 0.f);
                asm volatile("red.global.add.v2.f32 [%0], {%1, %2};"
                             :: "l"(o0 + j * 8), "f"(v0), "f"(v1) : "memory");
                asm volatile("red.global.add.v2.f32 [%0], {%1, %2};"
                             :: "l"(o1 + j * 8), "f"(v2), "f"(v3) : "memory");
            }
        }
        pb ^= 1;
    }
}

// ---------------- launch ----------------

extern "C" void kernel_launch(void* const* d_in, const int* in_sizes, int n_in,
                              void* d_out, int out_size) {
    const float* node_feat = (const float*)d_in[0];
    const float* edge_feat = (const float*)d_in[1];
    const int*   src_idx   = (const int*)d_in[2];
    const int*   tgt_idx   = (const int*)d_in[3];
    const float* W         = (const float*)d_in[4];
    const float* b         = (const float*)d_in[5];
    float* out = (float*)d_out;

    int n4 = NN_NODES * UNITS / 4;
    zero_out_kernel<<<(n4 + 255) / 256, 256>>>((float4*)out);

    static int configured = 0;
    if (!configured) {
        cudaFuncSetAttribute(edgeconv_kernel,
                             cudaFuncAttributeMaxDynamicSharedMemorySize, SM_TOTAL);
        configured = 1;
    }
    edgeconv_kernel<<<GRID_X, THREADS, SM_TOTAL>>>(
        node_feat, edge_feat, src_idx, tgt_idx, W, b, out);
}

// round 9
// speedup vs baseline: 4.1239x; 1.1572x over previous
#include <cuda_runtime.h>
#include <cuda_fp16.h>
#include <cstdint>

// ============================================================================
// ConvolutionFromEdgeSetUpdate:
//   messages = relu([node[src] | node[tgt] | edge] @ W + b)   (E x 64)
//   out      = segment_sum(messages, tgt, 50000)
// E=800000, D=64, U=64, K=192.
//
// R9 = R8 (201us best) with the A-side lo product dropped: SINGLE fp16
// product (A fp16, B fp16). Error = A+B fp16 quantization ~2.0e-4 (5x margin
// under the 1e-3 gate; R8 measured B-only = 1.44e-4). Halves HMMA count,
// A-ldsm, A-STS and convert math. Skeleton is R8-verbatim.
// ============================================================================

#define NN_NODES 50000
#define NN_EDGES 800000
#define D_FEAT   64
#define UNITS    64
#define KDIM     192
#define TILE_M   128
#define N_TILES  (NN_EDGES / TILE_M)   // 6250
#define THREADS  512                   // 16 warps: 8 m-groups x 2 n-groups
#define GRID_X   148

// SMEM: row-major fp16 tiles, row stride 200 halves = 400 B (16B-aligned,
// 400 mod 128 = 16 -> ldmatrix row sets bank-conflict-free).
#define STRIDE_B   400
#define SM_A       0
#define SM_B       (SM_A + TILE_M * STRIDE_B)        // 51200
#define SM_IDX     (SM_B + UNITS * STRIDE_B)         // 76800: 2 bufs x 256 int
#define SM_TOTAL   (SM_IDX + 2 * 256 * 4)            // 78848

// ---------------- helpers ----------------

__device__ __forceinline__ uint32_t smem_to_u32(const void* smem_ptr) {
    uint32_t addr;
    asm("{ .reg .u64 tmp; cvta.to.shared.u64 tmp, %1; cvt.u32.u64 %0, tmp; }"
        : "=r"(addr) : "l"(smem_ptr));
    return addr;
}

__device__ __forceinline__ void ldsm_x4(uint32_t* r, uint32_t addr) {
    asm volatile("ldmatrix.sync.aligned.m8n8.x4.shared.b16 {%0,%1,%2,%3}, [%4];"
        : "=r"(r[0]), "=r"(r[1]), "=r"(r[2]), "=r"(r[3]) : "r"(addr));
}

__device__ __forceinline__ void ldsm_x2(uint32_t* r, uint32_t addr) {
    asm volatile("ldmatrix.sync.aligned.m8n8.x2.shared.b16 {%0,%1}, [%2];"
        : "=r"(r[0]), "=r"(r[1]) : "r"(addr));
}

__device__ __forceinline__ void mma_f16(float* c, const uint32_t* a, const uint32_t* b) {
    asm volatile(
        "mma.sync.aligned.m16n8k16.row.col.f32.f16.f16.f32 "
        "{%0,%1,%2,%3}, {%4,%5,%6,%7}, {%8,%9}, {%0,%1,%2,%3};"
        : "+f"(c[0]), "+f"(c[1]), "+f"(c[2]), "+f"(c[3])
        : "r"(a[0]), "r"(a[1]), "r"(a[2]), "r"(a[3]), "r"(b[0]), "r"(b[1]));
}

__device__ __forceinline__ uint32_t pack_h2(float a, float b) {
    __half2 t = __halves2half2(__float2half_rn(a), __float2half_rn(b));
    return *reinterpret_cast<uint32_t*>(&t);
}

// ---------------- zero output (d_out is poisoned 0xAA) ----------------

__global__ void zero_out_kernel(float4* out) {
    int i = blockIdx.x * blockDim.x + threadIdx.x;
    if (i < NN_NODES * UNITS / 4) out[i] = make_float4(0.f, 0.f, 0.f, 0.f);
}

// ---------------- main fused kernel ----------------

__global__ __launch_bounds__(THREADS, 1)
void edgeconv_kernel(const float* __restrict__ node_feat,
                     const float* __restrict__ edge_feat,
                     const int*   __restrict__ src_idx,
                     const int*   __restrict__ tgt_idx,
                     const float* __restrict__ W,
                     const float* __restrict__ bias,
                     float*       __restrict__ out)
{
    extern __shared__ char smem[];
    const uint32_t smem_base = smem_to_u32(smem);
    const int tid  = threadIdx.x;
    const int wid  = tid >> 5;
    const int lane = tid & 31;

    int* const idx_sm = reinterpret_cast<int*>(smem + SM_IDX);

    // ---- build B = W^T (single fp16) in SMEM: Bsm[n][k], k contiguous ----
    for (int task = tid; task < 192; task += THREADS) {
        const int n = task & 63, bseg = task >> 6;
        char* rowp = smem + SM_B + n * STRIDE_B;
        #pragma unroll 8
        for (int j = 0; j < 64; ++j) {
            const int k = bseg * 64 + j;
            *reinterpret_cast<__half*>(rowp + k * 2) = __float2half_rn(W[k * UNITS + n]);
        }
    }

    // ---- stage indices for the first tile into buffer 0 ----
    if (tid < 256) {
        const int e = blockIdx.x * TILE_M + (tid & 127);
        idx_sm[tid] = (tid < 128) ? __ldg(src_idx + e) : __ldg(tgt_idx + e);
    }

    // warp tile: mg in {0..7} picks 16 rows, ng in {0,1} picks 32 cols
    const int mg = wid >> 1;
    const int ng = wid & 1;
    const int t4 = lane & 3;
    const int g  = lane >> 2;

    // per-thread bias for epilogue: cols ng*32 + j*8 + 2*t4 + {0,1}
    float bj0[4], bj1[4];
    #pragma unroll
    for (int j = 0; j < 4; ++j) {
        bj0[j] = bias[ng * 32 + j * 8 + 2 * t4];
        bj1[j] = bias[ng * 32 + j * 8 + 2 * t4 + 1];
    }

    // ldmatrix per-lane address components (byte offsets)
    const uint32_t a_lane_off =
        (uint32_t)((mg * 16 + (lane & 15)) * STRIDE_B + (lane >> 4) * 16);
    const uint32_t b_lane_off =
        (uint32_t)((ng * 32 + (lane & 7)) * STRIDE_B + ((lane >> 3) & 1) * 16);

    const uint32_t aA = smem_base + SM_A + a_lane_off;
    const uint32_t bB = smem_base + SM_B + b_lane_off;

    // coalesced gather mapping: 16 threads per (row,seg), one float4 each
    const int g_chunk = tid & 15;          // float4 index within 64-float row
    const int g_rs0   = tid >> 4;          // first rowseg (0..31), step 32

    __syncthreads();   // B tile + idx buf0 ready

    int pb = 0;
    for (int tile = blockIdx.x; tile < N_TILES; tile += GRID_X) {
        const int* idxp = idx_sm + pb * 256;

        // ===== gather + convert A tile (fp16): coalesced, batched MLP =====
        // rowsegs: 0..127 src rows, 128..255 tgt rows, 256..383 edge rows.
        // 32 rowsegs per pass x 12 passes, 2 batches of 6 independent LDG.128.
        #pragma unroll
        for (int half = 0; half < 2; ++half) {
            const float* p[6];
            int rowv[6], segv[6];
            #pragma unroll
            for (int i = 0; i < 6; ++i) {
                const int rs  = g_rs0 + (half * 6 + i) * 32;
                const int row = rs & (TILE_M - 1);
                const int seg = rs >> 7;
                rowv[i] = row; segv[i] = seg;
                p[i] = (seg == 2)
                     ? edge_feat + (size_t)(tile * TILE_M + row) * D_FEAT
                     : node_feat + (size_t)idxp[rs] * D_FEAT;
            }
            float4 v[6];
            #pragma unroll
            for (int i = 0; i < 6; ++i)
                v[i] = __ldg(reinterpret_cast<const float4*>(p[i]) + g_chunk);
            #pragma unroll
            for (int i = 0; i < 6; ++i) {
                uint2 hh;
                hh.x = pack_h2(v[i].x, v[i].y);
                hh.y = pack_h2(v[i].z, v[i].w);
                const uint32_t off =
                    (uint32_t)(rowv[i] * STRIDE_B + segv[i] * 128 + g_chunk * 8);
                *reinterpret_cast<uint2*>(smem + SM_A + off) = hh;
            }
        }
        __syncthreads();

        // ---- stage next tile's indices (LDG latency hides under MMA) ----
        {
            const int nxt = tile + GRID_X;
            if (nxt < N_TILES && tid < 256) {
                const int e = nxt * TILE_M + (tid & 127);
                idx_sm[(pb ^ 1) * 256 + tid] =
                    (tid < 128) ? __ldg(src_idx + e) : __ldg(tgt_idx + e);
            }
        }

        // ============ MMA: 16 rows x 32 cols per warp, K=192, 1 product =====
        float acc[4][4];
        #pragma unroll
        for (int j = 0; j < 4; ++j) {
            acc[j][0] = 0.f; acc[j][1] = 0.f; acc[j][2] = 0.f; acc[j][3] = 0.f;
        }

        #pragma unroll
        for (int ks = 0; ks < KDIM / 16; ++ks) {   // 12 k-steps
            const uint32_t kb = (uint32_t)(ks * 32);
            uint32_t aa[4];
            ldsm_x4(aa, aA + kb);
            #pragma unroll
            for (int j = 0; j < 4; ++j) {
                uint32_t bb[2];
                const uint32_t bj = (uint32_t)(j * 8 * STRIDE_B) + kb;
                ldsm_x2(bb, bB + bj);
                mma_f16(acc[j], aa, bb);
            }
        }
        __syncthreads();   // A tile + idx bufs consistent for next iteration

        // ============ epilogue: bias + relu + red.v2 scatter (as R8) ========
        {
            const int r0 = mg * 16 + g;
            const int tgt0 = idxp[128 + r0];
            const int tgt1 = idxp[128 + r0 + 8];
            float* o0 = out + (size_t)tgt0 * UNITS + ng * 32 + 2 * t4;
            float* o1 = out + (size_t)tgt1 * UNITS + ng * 32 + 2 * t4;
            #pragma unroll
            for (int j = 0; j < 4; ++j) {
                float v0 = fmaxf(acc[j][0] + bj0[j], 0.f);
                float v1 = fmaxf(acc[j][1] + bj1[j], 0.f);
                float v2 = fmaxf(acc[j][2] + bj0[j], 0.f);
                float v3 = fmaxf(acc[j][3] + bj1[j], 0.f);
                asm volatile("red.global.add.v2.f32 [%0], {%1, %2};"
                             :: "l"(o0 + j * 8), "f"(v0), "f"(v1) : "memory");
                asm volatile("red.global.add.v2.f32 [%0], {%1, %2};"
                             :: "l"(o1 + j * 8), "f"(v2), "f"(v3) : "memory");
            }
        }
        pb ^= 1;
    }
}

// ---------------- launch ----------------

extern "C" void kernel_launch(void* const* d_in, const int* in_sizes, int n_in,
                              void* d_out, int out_size) {
    const float* node_feat = (const float*)d_in[0];
    const float* edge_feat = (const float*)d_in[1];
    const int*   src_idx   = (const int*)d_in[2];
    const int*   tgt_idx   = (const int*)d_in[3];
    const float* W         = (const float*)d_in[4];
    const float* b         = (const float*)d_in[5];
    float* out = (float*)d_out;

    int n4 = NN_NODES * UNITS / 4;
    zero_out_kernel<<<(n4 + 255) / 256, 256>>>((float4*)out);

    static int configured = 0;
    if (!configured) {
        cudaFuncSetAttribute(edgeconv_kernel,
                             cudaFuncAttributeMaxDynamicSharedMemorySize, SM_TOTAL);
        configured = 1;
    }
    edgeconv_kernel<<<GRID_X, THREADS, SM_TOTAL>>>(
        node_feat, edge_feat, src_idx, tgt_idx, W, b, out);
}

// round 10
// speedup vs baseline: 4.8521x; 1.1766x over previous
#include <cuda_runtime.h>
#include <cuda_fp16.h>
#include <cstdint>

// ============================================================================
// ConvolutionFromEdgeSetUpdate:
//   messages = relu([node[src] | node[tgt] | edge] @ W + b)   (E x 64)
//   out      = segment_sum(messages, tgt, 50000)
// E=800000, D=64, U=64, K=192.
//
// R10 = R9 (174us best: single fp16 product) restructured as a 2-stage
// software pipeline: A tile double-buffered, gather(t+1) issued BEFORE MMA(t)
// so LDG/STS overlap ldsm/HMMA, ONE __syncthreads per tile (was 2), epilogue
// tgt indices pre-loaded into registers one iteration ahead.
// ============================================================================

#define NN_NODES 50000
#define NN_EDGES 800000
#define D_FEAT   64
#define UNITS    64
#define KDIM     192
#define TILE_M   128
#define N_TILES  (NN_EDGES / TILE_M)   // 6250
#define THREADS  512                   // 16 warps: 8 m-groups x 2 n-groups
#define GRID_X   148

// SMEM: row-major fp16 tiles, row stride 200 halves = 400 B (16B-aligned,
// 400 mod 128 = 16 -> ldmatrix row sets bank-conflict-free).
#define STRIDE_B   400
#define SM_A0      0
#define SM_A1      (SM_A0 + TILE_M * STRIDE_B)       // 51200
#define SM_B       (SM_A1 + TILE_M * STRIDE_B)       // 102400
#define SM_IDX     (SM_B + UNITS * STRIDE_B)         // 128000: 2 bufs x 256 int
#define SM_TOTAL   (SM_IDX + 2 * 256 * 4)            // 130048

// ---------------- helpers ----------------

__device__ __forceinline__ uint32_t smem_to_u32(const void* smem_ptr) {
    uint32_t addr;
    asm("{ .reg .u64 tmp; cvta.to.shared.u64 tmp, %1; cvt.u32.u64 %0, tmp; }"
        : "=r"(addr) : "l"(smem_ptr));
    return addr;
}

__device__ __forceinline__ void ldsm_x4(uint32_t* r, uint32_t addr) {
    asm volatile("ldmatrix.sync.aligned.m8n8.x4.shared.b16 {%0,%1,%2,%3}, [%4];"
        : "=r"(r[0]), "=r"(r[1]), "=r"(r[2]), "=r"(r[3]) : "r"(addr));
}

__device__ __forceinline__ void ldsm_x2(uint32_t* r, uint32_t addr) {
    asm volatile("ldmatrix.sync.aligned.m8n8.x2.shared.b16 {%0,%1}, [%2];"
        : "=r"(r[0]), "=r"(r[1]) : "r"(addr));
}

__device__ __forceinline__ void mma_f16(float* c, const uint32_t* a, const uint32_t* b) {
    asm volatile(
        "mma.sync.aligned.m16n8k16.row.col.f32.f16.f16.f32 "
        "{%0,%1,%2,%3}, {%4,%5,%6,%7}, {%8,%9}, {%0,%1,%2,%3};"
        : "+f"(c[0]), "+f"(c[1]), "+f"(c[2]), "+f"(c[3])
        : "r"(a[0]), "r"(a[1]), "r"(a[2]), "r"(a[3]), "r"(b[0]), "r"(b[1]));
}

__device__ __forceinline__ uint32_t pack_h2(float a, float b) {
    __half2 t = __halves2half2(__float2half_rn(a), __float2half_rn(b));
    return *reinterpret_cast<uint32_t*>(&t);
}

// ---------------- zero output (d_out is poisoned 0xAA) ----------------

__global__ void zero_out_kernel(float4* out) {
    int i = blockIdx.x * blockDim.x + threadIdx.x;
    if (i < NN_NODES * UNITS / 4) out[i] = make_float4(0.f, 0.f, 0.f, 0.f);
}

// ---------------- main fused kernel ----------------

__global__ __launch_bounds__(THREADS, 1)
void edgeconv_kernel(const float* __restrict__ node_feat,
                     const float* __restrict__ edge_feat,
                     const int*   __restrict__ src_idx,
                     const int*   __restrict__ tgt_idx,
                     const float* __restrict__ W,
                     const float* __restrict__ bias,
                     float*       __restrict__ out)
{
    extern __shared__ char smem[];
    const uint32_t smem_base = smem_to_u32(smem);
    const int tid  = threadIdx.x;
    const int wid  = tid >> 5;
    const int lane = tid & 31;

    int* const idx_sm = reinterpret_cast<int*>(smem + SM_IDX);

    // ---- build B = W^T (single fp16) in SMEM: Bsm[n][k], k contiguous ----
    for (int task = tid; task < 192; task += THREADS) {
        const int n = task & 63, bseg = task >> 6;
        char* rowp = smem + SM_B + n * STRIDE_B;
        #pragma unroll 8
        for (int j = 0; j < 64; ++j) {
            const int k = bseg * 64 + j;
            *reinterpret_cast<__half*>(rowp + k * 2) = __float2half_rn(W[k * UNITS + n]);
        }
    }

    // warp tile: mg in {0..7} picks 16 rows, ng in {0,1} picks 32 cols
    const int mg = wid >> 1;
    const int ng = wid & 1;
    const int t4 = lane & 3;
    const int g  = lane >> 2;
    const int r0 = mg * 16 + g;           // epilogue row within tile

    // per-thread bias for epilogue: cols ng*32 + j*8 + 2*t4 + {0,1}
    float bj0[4], bj1[4];
    #pragma unroll
    for (int j = 0; j < 4; ++j) {
        bj0[j] = bias[ng * 32 + j * 8 + 2 * t4];
        bj1[j] = bias[ng * 32 + j * 8 + 2 * t4 + 1];
    }

    // ldmatrix per-lane address components (byte offsets)
    const uint32_t a_lane_off =
        (uint32_t)((mg * 16 + (lane & 15)) * STRIDE_B + (lane >> 4) * 16);
    const uint32_t b_lane_off =
        (uint32_t)((ng * 32 + (lane & 7)) * STRIDE_B + ((lane >> 3) & 1) * 16);

    const uint32_t bB = smem_base + SM_B + b_lane_off;

    // coalesced gather mapping: 16 threads per (row,seg), one float4 each
    const int g_chunk = tid & 15;          // float4 index within 64-float row
    const int g_rs0   = tid >> 4;          // first rowseg (0..31), step 32

    // ======== prologue: idx(t0) -> buf0 ========
    const int tile0 = blockIdx.x;
    if (tid < 256) {
        const int e = tile0 * TILE_M + (tid & 127);
        idx_sm[tid] = (tid < 128) ? __ldg(src_idx + e) : __ldg(tgt_idx + e);
    }
    __syncthreads();   // B + idx(t0) ready

    // gather(t0) -> A buf0; read tgt regs for t0; stage idx(t0+G) -> buf1
    {
        const int* idxp = idx_sm;          // buf 0
        #pragma unroll
        for (int half = 0; half < 2; ++half) {
            const float* p[6]; int rowv[6], segv[6];
            #pragma unroll
            for (int i = 0; i < 6; ++i) {
                const int rs  = g_rs0 + (half * 6 + i) * 32;
                const int row = rs & (TILE_M - 1);
                const int seg = rs >> 7;
                rowv[i] = row; segv[i] = seg;
                p[i] = (seg == 2)
                     ? edge_feat + (size_t)(tile0 * TILE_M + row) * D_FEAT
                     : node_feat + (size_t)idxp[rs] * D_FEAT;
            }
            float4 v[6];
            #pragma unroll
            for (int i = 0; i < 6; ++i)
                v[i] = __ldg(reinterpret_cast<const float4*>(p[i]) + g_chunk);
            #pragma unroll
            for (int i = 0; i < 6; ++i) {
                uint2 hh;
                hh.x = pack_h2(v[i].x, v[i].y);
                hh.y = pack_h2(v[i].z, v[i].w);
                const uint32_t off =
                    (uint32_t)(rowv[i] * STRIDE_B + segv[i] * 128 + g_chunk * 8);
                *reinterpret_cast<uint2*>(smem + SM_A0 + off) = hh;
            }
        }
    }
    int tgtr0 = idx_sm[128 + r0];
    int tgtr1 = idx_sm[128 + r0 + 8];
    if (tid < 256 && tile0 + GRID_X < N_TILES) {
        const int e = (tile0 + GRID_X) * TILE_M + (tid & 127);
        idx_sm[256 + tid] = (tid < 128) ? __ldg(src_idx + e) : __ldg(tgt_idx + e);
    }
    __syncthreads();   // A buf0 + idx(t0+G) ready

    // ======== pipelined main loop: one barrier per tile ========
    int p = 0, q = 0;
    for (int tile = tile0; tile < N_TILES; tile += GRID_X) {
        const int nxt = tile + GRID_X;
        int ntgt0 = 0, ntgt1 = 0;

        // ---- stage 1: gather(nxt) into A buf p^1 (LDGs overlap MMA below) --
        if (nxt < N_TILES) {
            const int* idxp = idx_sm + (q ^ 1) * 256;
            const uint32_t abase = (p ^ 1) ? SM_A1 : SM_A0;
            #pragma unroll
            for (int half = 0; half < 2; ++half) {
                const float* pp[6]; int rowv[6], segv[6];
                #pragma unroll
                for (int i = 0; i < 6; ++i) {
                    const int rs  = g_rs0 + (half * 6 + i) * 32;
                    const int row = rs & (TILE_M - 1);
                    const int seg = rs >> 7;
                    rowv[i] = row; segv[i] = seg;
                    pp[i] = (seg == 2)
                         ? edge_feat + (size_t)(nxt * TILE_M + row) * D_FEAT
                         : node_feat + (size_t)idxp[rs] * D_FEAT;
                }
                float4 v[6];
                #pragma unroll
                for (int i = 0; i < 6; ++i)
                    v[i] = __ldg(reinterpret_cast<const float4*>(pp[i]) + g_chunk);
                #pragma unroll
                for (int i = 0; i < 6; ++i) {
                    uint2 hh;
                    hh.x = pack_h2(v[i].x, v[i].y);
                    hh.y = pack_h2(v[i].z, v[i].w);
                    const uint32_t off =
                        (uint32_t)(rowv[i] * STRIDE_B + segv[i] * 128 + g_chunk * 8);
                    *reinterpret_cast<uint2*>(smem + abase + off) = hh;
                }
            }
            // epilogue tgt regs for nxt (read now; buffer q^1 survives to next iter)
            ntgt0 = idxp[128 + r0];
            ntgt1 = idxp[128 + r0 + 8];
            // stage idx(nxt+G) into buf q (its old contents are dead now)
            if (tid < 256 && nxt + GRID_X < N_TILES) {
                const int e = (nxt + GRID_X) * TILE_M + (tid & 127);
                idx_sm[q * 256 + tid] =
                    (tid < 128) ? __ldg(src_idx + e) : __ldg(tgt_idx + e);
            }
        }

        // ---- stage 2: MMA(tile) from A buf p ----
        const uint32_t aA = smem_base + (p ? SM_A1 : SM_A0) + a_lane_off;
        float acc[4][4];
        #pragma unroll
        for (int j = 0; j < 4; ++j) {
            acc[j][0] = 0.f; acc[j][1] = 0.f; acc[j][2] = 0.f; acc[j][3] = 0.f;
        }
        #pragma unroll
        for (int ks = 0; ks < KDIM / 16; ++ks) {   // 12 k-steps
            const uint32_t kb = (uint32_t)(ks * 32);
            uint32_t aa[4];
            ldsm_x4(aa, aA + kb);
            #pragma unroll
            for (int j = 0; j < 4; ++j) {
                uint32_t bb[2];
                const uint32_t bj = (uint32_t)(j * 8 * STRIDE_B) + kb;
                ldsm_x2(bb, bB + bj);
                mma_f16(acc[j], aa, bb);
            }
        }

        // ---- epilogue(tile): bias + relu + red.v2 scatter ----
        {
            float* o0 = out + (size_t)tgtr0 * UNITS + ng * 32 + 2 * t4;
            float* o1 = out + (size_t)tgtr1 * UNITS + ng * 32 + 2 * t4;
            #pragma unroll
            for (int j = 0; j < 4; ++j) {
                float v0 = fmaxf(acc[j][0] + bj0[j], 0.f);
                float v1 = fmaxf(acc[j][1] + bj1[j], 0.f);
                float v2 = fmaxf(acc[j][2] + bj0[j], 0.f);
                float v3 = fmaxf(acc[j][3] + bj1[j], 0.f);
                asm volatile("red.global.add.v2.f32 [%0], {%1, %2};"
                             :: "l"(o0 + j * 8), "f"(v0), "f"(v1) : "memory");
                asm volatile("red.global.add.v2.f32 [%0], {%1, %2};"
                             :: "l"(o1 + j * 8), "f"(v2), "f"(v3) : "memory");
            }
        }

        __syncthreads();   // A buf p^1 written, idx buf q staged, buf p free
        tgtr0 = ntgt0; tgtr1 = ntgt1;
        p ^= 1; q ^= 1;
    }
}

// ---------------- launch ----------------

extern "C" void kernel_launch(void* const* d_in, const int* in_sizes, int n_in,
                              void* d_out, int out_size) {
    const float* node_feat = (const float*)d_in[0];
    const float* edge_feat = (const float*)d_in[1];
    const int*   src_idx   = (const int*)d_in[2];
    const int*   tgt_idx   = (const int*)d_in[3];
    const float* W         = (const float*)d_in[4];
    const float* b         = (const float*)d_in[5];
    float* out = (float*)d_out;

    int n4 = NN_NODES * UNITS / 4;
    zero_out_kernel<<<(n4 + 255) / 256, 256>>>((float4*)out);

    static int configured = 0;
    if (!configured) {
        cudaFuncSetAttribute(edgeconv_kernel,
                             cudaFuncAttributeMaxDynamicSharedMemorySize, SM_TOTAL);
        configured = 1;
    }
    edgeconv_kernel<<<GRID_X, THREADS, SM_TOTAL>>>(
        node_feat, edge_feat, src_idx, tgt_idx, W, b, out);
}

// round 11
// speedup vs baseline: 4.9352x; 1.0171x over previous
#include <cuda_runtime.h>
#include <cuda_fp16.h>
#include <cstdint>

// ============================================================================
// ConvolutionFromEdgeSetUpdate:
//   messages = relu([node[src] | node[tgt] | edge] @ W + b)   (E x 64)
//   out      = segment_sum(messages, tgt, 50000)
// E=800000, D=64, U=64, K=192.
//
// R11 = R10 (148us best: fp16 single product, 2-stage pipelined, 1 barrier
// per tile) halved per-CTA: TILE_M=64, 256 threads (8 warps), GRID 296 ->
// 2 CTAs/SM (occ 50%). Same per-edge byte counts; the doubled warp pool
// pushes L1 from 68% busy toward saturation.
// ============================================================================

#define NN_NODES 50000
#define NN_EDGES 800000
#define D_FEAT   64
#define UNITS    64
#define KDIM     192
#define TILE_M   64
#define N_TILES  (NN_EDGES / TILE_M)   // 12500
#define THREADS  256                   // 8 warps: 4 m-groups x 2 n-groups
#define GRID_X   296                   // 2 CTAs per SM

// SMEM: row-major fp16 tiles, row stride 200 halves = 400 B (16B-aligned,
// 400 mod 128 = 16 -> ldmatrix row sets bank-conflict-free).
#define STRIDE_B   400
#define SM_A0      0
#define SM_A1      (SM_A0 + TILE_M * STRIDE_B)       // 25600
#define SM_B       (SM_A1 + TILE_M * STRIDE_B)       // 51200
#define SM_IDX     (SM_B + UNITS * STRIDE_B)         // 76800: 2 bufs x 128 int
#define SM_TOTAL   (SM_IDX + 2 * 128 * 4)            // 77824 -> 2 CTAs/SM

// ---------------- helpers ----------------

__device__ __forceinline__ uint32_t smem_to_u32(const void* smem_ptr) {
    uint32_t addr;
    asm("{ .reg .u64 tmp; cvta.to.shared.u64 tmp, %1; cvt.u32.u64 %0, tmp; }"
        : "=r"(addr) : "l"(smem_ptr));
    return addr;
}

__device__ __forceinline__ void ldsm_x4(uint32_t* r, uint32_t addr) {
    asm volatile("ldmatrix.sync.aligned.m8n8.x4.shared.b16 {%0,%1,%2,%3}, [%4];"
        : "=r"(r[0]), "=r"(r[1]), "=r"(r[2]), "=r"(r[3]) : "r"(addr));
}

__device__ __forceinline__ void ldsm_x2(uint32_t* r, uint32_t addr) {
    asm volatile("ldmatrix.sync.aligned.m8n8.x2.shared.b16 {%0,%1}, [%2];"
        : "=r"(r[0]), "=r"(r[1]) : "r"(addr));
}

__device__ __forceinline__ void mma_f16(float* c, const uint32_t* a, const uint32_t* b) {
    asm volatile(
        "mma.sync.aligned.m16n8k16.row.col.f32.f16.f16.f32 "
        "{%0,%1,%2,%3}, {%4,%5,%6,%7}, {%8,%9}, {%0,%1,%2,%3};"
        : "+f"(c[0]), "+f"(c[1]), "+f"(c[2]), "+f"(c[3])
        : "r"(a[0]), "r"(a[1]), "r"(a[2]), "r"(a[3]), "r"(b[0]), "r"(b[1]));
}

__device__ __forceinline__ uint32_t pack_h2(float a, float b) {
    __half2 t = __halves2half2(__float2half_rn(a), __float2half_rn(b));
    return *reinterpret_cast<uint32_t*>(&t);
}

// ---------------- zero output (d_out is poisoned 0xAA) ----------------

__global__ void zero_out_kernel(float4* out) {
    int i = blockIdx.x * blockDim.x + threadIdx.x;
    if (i < NN_NODES * UNITS / 4) out[i] = make_float4(0.f, 0.f, 0.f, 0.f);
}

// ---------------- main fused kernel ----------------

__global__ __launch_bounds__(THREADS, 2)
void edgeconv_kernel(const float* __restrict__ node_feat,
                     const float* __restrict__ edge_feat,
                     const int*   __restrict__ src_idx,
                     const int*   __restrict__ tgt_idx,
                     const float* __restrict__ W,
                     const float* __restrict__ bias,
                     float*       __restrict__ out)
{
    extern __shared__ char smem[];
    const uint32_t smem_base = smem_to_u32(smem);
    const int tid  = threadIdx.x;
    const int wid  = tid >> 5;
    const int lane = tid & 31;

    int* const idx_sm = reinterpret_cast<int*>(smem + SM_IDX);

    // ---- build B = W^T (single fp16) in SMEM: Bsm[n][k], k contiguous ----
    for (int task = tid; task < 192; task += THREADS) {
        const int n = task & 63, bseg = task >> 6;
        char* rowp = smem + SM_B + n * STRIDE_B;
        #pragma unroll 8
        for (int j = 0; j < 64; ++j) {
            const int k = bseg * 64 + j;
            *reinterpret_cast<__half*>(rowp + k * 2) = __float2half_rn(W[k * UNITS + n]);
        }
    }

    // warp tile: mg in {0..3} picks 16 rows, ng in {0,1} picks 32 cols
    const int mg = wid >> 1;
    const int ng = wid & 1;
    const int t4 = lane & 3;
    const int g  = lane >> 2;
    const int r0 = mg * 16 + g;           // epilogue row within tile (0..63)

    // per-thread bias for epilogue: cols ng*32 + j*8 + 2*t4 + {0,1}
    float bj0[4], bj1[4];
    #pragma unroll
    for (int j = 0; j < 4; ++j) {
        bj0[j] = bias[ng * 32 + j * 8 + 2 * t4];
        bj1[j] = bias[ng * 32 + j * 8 + 2 * t4 + 1];
    }

    // ldmatrix per-lane address components (byte offsets)
    const uint32_t a_lane_off =
        (uint32_t)((mg * 16 + (lane & 15)) * STRIDE_B + (lane >> 4) * 16);
    const uint32_t b_lane_off =
        (uint32_t)((ng * 32 + (lane & 7)) * STRIDE_B + ((lane >> 3) & 1) * 16);

    const uint32_t bB = smem_base + SM_B + b_lane_off;

    // coalesced gather mapping: 16 threads per (row,seg), one float4 each
    const int g_chunk = tid & 15;          // float4 index within 64-float row
    const int g_rs0   = tid >> 4;          // first rowseg (0..15), step 16

    // ======== prologue: idx(t0) -> buf0 ========
    const int tile0 = blockIdx.x;
    if (tid < 128) {
        const int e = tile0 * TILE_M + (tid & 63);
        idx_sm[tid] = (tid < 64) ? __ldg(src_idx + e) : __ldg(tgt_idx + e);
    }
    __syncthreads();   // B + idx(t0) ready

    // gather(t0) -> A buf0; read tgt regs for t0; stage idx(t0+G) -> buf1
    {
        const int* idxp = idx_sm;          // buf 0
        #pragma unroll
        for (int half = 0; half < 2; ++half) {
            const float* p[6]; int rowv[6], segv[6];
            #pragma unroll
            for (int i = 0; i < 6; ++i) {
                const int rs  = g_rs0 + (half * 6 + i) * 16;
                const int row = rs & (TILE_M - 1);
                const int seg = rs >> 6;
                rowv[i] = row; segv[i] = seg;
                p[i] = (seg == 2)
                     ? edge_feat + (size_t)(tile0 * TILE_M + row) * D_FEAT
                     : node_feat + (size_t)idxp[rs] * D_FEAT;
            }
            float4 v[6];
            #pragma unroll
            for (int i = 0; i < 6; ++i)
                v[i] = __ldg(reinterpret_cast<const float4*>(p[i]) + g_chunk);
            #pragma unroll
            for (int i = 0; i < 6; ++i) {
                uint2 hh;
                hh.x = pack_h2(v[i].x, v[i].y);
                hh.y = pack_h2(v[i].z, v[i].w);
                const uint32_t off =
                    (uint32_t)(rowv[i] * STRIDE_B + segv[i] * 128 + g_chunk * 8);
                *reinterpret_cast<uint2*>(smem + SM_A0 + off) = hh;
            }
        }
    }
    int tgtr0 = idx_sm[64 + r0];
    int tgtr1 = idx_sm[64 + r0 + 8];
    if (tid < 128 && tile0 + GRID_X < N_TILES) {
        const int e = (tile0 + GRID_X) * TILE_M + (tid & 63);
        idx_sm[128 + tid] = (tid < 64) ? __ldg(src_idx + e) : __ldg(tgt_idx + e);
    }
    __syncthreads();   // A buf0 + idx(t0+G) ready

    // ======== pipelined main loop: one barrier per tile ========
    int p = 0, q = 0;
    for (int tile = tile0; tile < N_TILES; tile += GRID_X) {
        const int nxt = tile + GRID_X;
        int ntgt0 = 0, ntgt1 = 0;

        // ---- stage 1: gather(nxt) into A buf p^1 (LDGs overlap MMA below) --
        if (nxt < N_TILES) {
            const int* idxp = idx_sm + (q ^ 1) * 128;
            const uint32_t abase = (p ^ 1) ? SM_A1 : SM_A0;
            #pragma unroll
            for (int half = 0; half < 2; ++half) {
                const float* pp[6]; int rowv[6], segv[6];
                #pragma unroll
                for (int i = 0; i < 6; ++i) {
                    const int rs  = g_rs0 + (half * 6 + i) * 16;
                    const int row = rs & (TILE_M - 1);
                    const int seg = rs >> 6;
                    rowv[i] = row; segv[i] = seg;
                    pp[i] = (seg == 2)
                         ? edge_feat + (size_t)(nxt * TILE_M + row) * D_FEAT
                         : node_feat + (size_t)idxp[rs] * D_FEAT;
                }
                float4 v[6];
                #pragma unroll
                for (int i = 0; i < 6; ++i)
                    v[i] = __ldg(reinterpret_cast<const float4*>(pp[i]) + g_chunk);
                #pragma unroll
                for (int i = 0; i < 6; ++i) {
                    uint2 hh;
                    hh.x = pack_h2(v[i].x, v[i].y);
                    hh.y = pack_h2(v[i].z, v[i].w);
                    const uint32_t off =
                        (uint32_t)(rowv[i] * STRIDE_B + segv[i] * 128 + g_chunk * 8);
                    *reinterpret_cast<uint2*>(smem + abase + off) = hh;
                }
            }
            // epilogue tgt regs for nxt (read now; buffer q^1 survives to next iter)
            ntgt0 = idxp[64 + r0];
            ntgt1 = idxp[64 + r0 + 8];
            // stage idx(nxt+G) into buf q (its old contents are dead now)
            if (tid < 128 && nxt + GRID_X < N_TILES) {
                const int e = (nxt + GRID_X) * TILE_M + (tid & 63);
                idx_sm[q * 128 + tid] =
                    (tid < 64) ? __ldg(src_idx + e) : __ldg(tgt_idx + e);
            }
        }

        // ---- stage 2: MMA(tile) from A buf p ----
        const uint32_t aA = smem_base + (p ? SM_A1 : SM_A0) + a_lane_off;
        float acc[4][4];
        #pragma unroll
        for (int j = 0; j < 4; ++j) {
            acc[j][0] = 0.f; acc[j][1] = 0.f; acc[j][2] = 0.f; acc[j][3] = 0.f;
        }
        #pragma unroll
        for (int ks = 0; ks < KDIM / 16; ++ks) {   // 12 k-steps
            const uint32_t kb = (uint32_t)(ks * 32);
            uint32_t aa[4];
            ldsm_x4(aa, aA + kb);
            #pragma unroll
            for (int j = 0; j < 4; ++j) {
                uint32_t bb[2];
                const uint32_t bj = (uint32_t)(j * 8 * STRIDE_B) + kb;
                ldsm_x2(bb, bB + bj);
                mma_f16(acc[j], aa, bb);
            }
        }

        // ---- epilogue(tile): bias + relu + red.v2 scatter ----
        {
            float* o0 = out + (size_t)tgtr0 * UNITS + ng * 32 + 2 * t4;
            float* o1 = out + (size_t)tgtr1 * UNITS + ng * 32 + 2 * t4;
            #pragma unroll
            for (int j = 0; j < 4; ++j) {
                float v0 = fmaxf(acc[j][0] + bj0[j], 0.f);
                float v1 = fmaxf(acc[j][1] + bj1[j], 0.f);
                float v2 = fmaxf(acc[j][2] + bj0[j], 0.f);
                float v3 = fmaxf(acc[j][3] + bj1[j], 0.f);
                asm volatile("red.global.add.v2.f32 [%0], {%1, %2};"
                             :: "l"(o0 + j * 8), "f"(v0), "f"(v1) : "memory");
                asm volatile("red.global.add.v2.f32 [%0], {%1, %2};"
                             :: "l"(o1 + j * 8), "f"(v2), "f"(v3) : "memory");
            }
        }

        __syncthreads();   // A buf p^1 written, idx buf q staged, buf p free
        tgtr0 = ntgt0; tgtr1 = ntgt1;
        p ^= 1; q ^= 1;
    }
}

// ---------------- launch ----------------

extern "C" void kernel_launch(void* const* d_in, const int* in_sizes, int n_in,
                              void* d_out, int out_size) {
    const float* node_feat = (const float*)d_in[0];
    const float* edge_feat = (const float*)d_in[1];
    const int*   src_idx   = (const int*)d_in[2];
    const int*   tgt_idx   = (const int*)d_in[3];
    const float* W         = (const float*)d_in[4];
    const float* b         = (const float*)d_in[5];
    float* out = (float*)d_out;

    int n4 = NN_NODES * UNITS / 4;
    zero_out_kernel<<<(n4 + 255) / 256, 256>>>((float4*)out);

    static int configured = 0;
    if (!configured) {
        cudaFuncSetAttribute(edgeconv_kernel,
                             cudaFuncAttributeMaxDynamicSharedMemorySize, SM_TOTAL);
        configured = 1;
    }
    edgeconv_kernel<<<GRID_X, THREADS, SM_TOTAL>>>(
        node_feat, edge_feat, src_idx, tgt_idx, W, b, out);
}

// round 12
// speedup vs baseline: 4.9428x; 1.0015x over previous
#include <cuda_runtime.h>
#include <cuda_fp16.h>
#include <cstdint>

// ============================================================================
// ConvolutionFromEdgeSetUpdate:
//   messages = relu([node[src] | node[tgt] | edge] @ W + b)   (E x 64)
//   out      = segment_sum(messages, tgt, 50000)
// E=800000, D=64, U=64, K=192.
//
// R12 = R11 (145.7us best) with split-K + register-resident B:
//   8 warps = mg(2) x ng(2) x kg(2); warp tile 32 rows x 32 cols x 96 k.
//   B frags preloaded ONCE into 48 regs -> steady-state B-ldsm (40% of L1
//   traffic) eliminated. kg partners (wid^1) swap one 16-row acc block via
//   padded SMEM so partial sums combine BEFORE relu; every warp epilogues
//   16 rows (red traffic unchanged). 2 barriers/tile.
// ============================================================================

#define NN_NODES 50000
#define NN_EDGES 800000
#define D_FEAT   64
#define UNITS    64
#define KDIM     192
#define TILE_M   64
#define N_TILES  (NN_EDGES / TILE_M)   // 12500
#define THREADS  256                   // 8 warps: 2 mg x 2 ng x 2 kg
#define GRID_X   296                   // 2 CTAs per SM

// SMEM: row-major fp16 tiles, row stride 200 halves = 400 B (16B-aligned,
// 400 mod 128 = 16 -> ldmatrix row sets bank-conflict-free).
#define STRIDE_B   400
#define SM_A0      0
#define SM_A1      (SM_A0 + TILE_M * STRIDE_B)       // 25600
#define SM_B       (SM_A1 + TILE_M * STRIDE_B)       // 51200
#define SM_IDX     (SM_B + UNITS * STRIDE_B)         // 76800: 2 bufs x 128 int
#define SM_P       (SM_IDX + 2 * 128 * 4)            // 77824: 8 slots x 2560 B
#define SM_TOTAL   (SM_P + 8 * 2560)                 // 98304 -> 2 CTAs/SM

// ---------------- helpers ----------------

__device__ __forceinline__ uint32_t smem_to_u32(const void* smem_ptr) {
    uint32_t addr;
    asm("{ .reg .u64 tmp; cvta.to.shared.u64 tmp, %1; cvt.u32.u64 %0, tmp; }"
        : "=r"(addr) : "l"(smem_ptr));
    return addr;
}

__device__ __forceinline__ void ldsm_x4(uint32_t* r, uint32_t addr) {
    asm volatile("ldmatrix.sync.aligned.m8n8.x4.shared.b16 {%0,%1,%2,%3}, [%4];"
        : "=r"(r[0]), "=r"(r[1]), "=r"(r[2]), "=r"(r[3]) : "r"(addr));
}

__device__ __forceinline__ void ldsm_x2(uint32_t* r, uint32_t addr) {
    asm volatile("ldmatrix.sync.aligned.m8n8.x2.shared.b16 {%0,%1}, [%2];"
        : "=r"(r[0]), "=r"(r[1]) : "r"(addr));
}

__device__ __forceinline__ void mma_f16(float* c, const uint32_t* a, const uint32_t* b) {
    asm volatile(
        "mma.sync.aligned.m16n8k16.row.col.f32.f16.f16.f32 "
        "{%0,%1,%2,%3}, {%4,%5,%6,%7}, {%8,%9}, {%0,%1,%2,%3};"
        : "+f"(c[0]), "+f"(c[1]), "+f"(c[2]), "+f"(c[3])
        : "r"(a[0]), "r"(a[1]), "r"(a[2]), "r"(a[3]), "r"(b[0]), "r"(b[1]));
}

__device__ __forceinline__ uint32_t pack_h2(float a, float b) {
    __half2 t = __halves2half2(__float2half_rn(a), __float2half_rn(b));
    return *reinterpret_cast<uint32_t*>(&t);
}

// ---------------- zero output (d_out is poisoned 0xAA) ----------------

__global__ void zero_out_kernel(float4* out) {
    int i = blockIdx.x * blockDim.x + threadIdx.x;
    if (i < NN_NODES * UNITS / 4) out[i] = make_float4(0.f, 0.f, 0.f, 0.f);
}

// ---------------- main fused kernel ----------------

__global__ __launch_bounds__(THREADS, 2)
void edgeconv_kernel(const float* __restrict__ node_feat,
                     const float* __restrict__ edge_feat,
                     const int*   __restrict__ src_idx,
                     const int*   __restrict__ tgt_idx,
                     const float* __restrict__ W,
                     const float* __restrict__ bias,
                     float*       __restrict__ out)
{
    extern __shared__ char smem[];
    const uint32_t smem_base = smem_to_u32(smem);
    const int tid  = threadIdx.x;
    const int wid  = tid >> 5;
    const int lane = tid & 31;

    int* const idx_sm = reinterpret_cast<int*>(smem + SM_IDX);

    // ---- build B = W^T (single fp16) in SMEM: Bsm[n][k], k contiguous ----
    for (int task = tid; task < 192; task += THREADS) {
        const int n = task & 63, bseg = task >> 6;
        char* rowp = smem + SM_B + n * STRIDE_B;
        #pragma unroll 8
        for (int j = 0; j < 64; ++j) {
            const int k = bseg * 64 + j;
            *reinterpret_cast<__half*>(rowp + k * 2) = __float2half_rn(W[k * UNITS + n]);
        }
    }

    // warp decomposition: mg(2) x ng(2) x kg(2)
    const int mg = wid >> 2;
    const int ng = (wid >> 1) & 1;
    const int kg = wid & 1;
    const int t4 = lane & 3;
    const int g  = lane >> 2;
    const int r0 = mg * 32 + kg * 16 + g;   // kept epilogue row (0..63)

    // per-thread bias: cols ng*32 + nb*8 + 2*t4 + {0,1}
    float bj0[4], bj1[4];
    #pragma unroll
    for (int j = 0; j < 4; ++j) {
        bj0[j] = bias[ng * 32 + j * 8 + 2 * t4];
        bj1[j] = bias[ng * 32 + j * 8 + 2 * t4 + 1];
    }

    // ldmatrix lane offsets. k byte offset for this warp's half: kg*96*2 = kg*192.
    // kept A rows = mg*32 + kg*16 ; give-away rows = mg*32 + (1-kg)*16.
    const uint32_t aoffK =
        (uint32_t)((mg * 32 + kg * 16 + (lane & 15)) * STRIDE_B
                   + (lane >> 4) * 16 + kg * 192);
    const uint32_t aoffG =
        (uint32_t)((mg * 32 + (1 - kg) * 16 + (lane & 15)) * STRIDE_B
                   + (lane >> 4) * 16 + kg * 192);
    const uint32_t bB = smem_base + SM_B
        + (uint32_t)((ng * 32 + (lane & 7)) * STRIDE_B
                     + ((lane >> 3) & 1) * 16 + kg * 192);

    // partial-exchange slots (20-float lane stride: conflict-free 16B ops)
    char* const myslot = smem + SM_P + wid * 2560 + lane * 80;
    char* const prslot = smem + SM_P + (wid ^ 1) * 2560 + lane * 80;

    // coalesced gather mapping: 16 threads per (row,seg), one float4 each
    const int g_chunk = tid & 15;
    const int g_rs0   = tid >> 4;

    // ======== prologue: idx(t0) -> buf0 ========
    const int tile0 = blockIdx.x;
    if (tid < 128) {
        const int e = tile0 * TILE_M + (tid & 63);
        idx_sm[tid] = (tid < 64) ? __ldg(src_idx + e) : __ldg(tgt_idx + e);
    }
    __syncthreads();   // B tile + idx(t0) ready

    // ---- preload B frags ONCE: 6 ks x 4 nb x 2 regs = 48 regs ----
    uint32_t breg[6][4][2];
    #pragma unroll
    for (int ks = 0; ks < 6; ++ks)
        #pragma unroll
        for (int nb = 0; nb < 4; ++nb)
            ldsm_x2(breg[ks][nb], bB + (uint32_t)(nb * 8 * STRIDE_B + ks * 32));

    // gather(t0) -> A buf0; tgt regs for t0; stage idx(t0+G) -> buf1
    {
        const int* idxp = idx_sm;
        #pragma unroll
        for (int half = 0; half < 2; ++half) {
            const float* p[6]; int rowv[6], segv[6];
            #pragma unroll
            for (int i = 0; i < 6; ++i) {
                const int rs  = g_rs0 + (half * 6 + i) * 16;
                const int row = rs & (TILE_M - 1);
                const int seg = rs >> 6;
                rowv[i] = row; segv[i] = seg;
                p[i] = (seg == 2)
                     ? edge_feat + (size_t)(tile0 * TILE_M + row) * D_FEAT
                     : node_feat + (size_t)idxp[rs] * D_FEAT;
            }
            float4 v[6];
            #pragma unroll
            for (int i = 0; i < 6; ++i)
                v[i] = __ldg(reinterpret_cast<const float4*>(p[i]) + g_chunk);
            #pragma unroll
            for (int i = 0; i < 6; ++i) {
                uint2 hh;
                hh.x = pack_h2(v[i].x, v[i].y);
                hh.y = pack_h2(v[i].z, v[i].w);
                const uint32_t off =
                    (uint32_t)(rowv[i] * STRIDE_B + segv[i] * 128 + g_chunk * 8);
                *reinterpret_cast<uint2*>(smem + SM_A0 + off) = hh;
            }
        }
    }
    int tgtr0 = idx_sm[64 + r0];
    int tgtr1 = idx_sm[64 + r0 + 8];
    if (tid < 128 && tile0 + GRID_X < N_TILES) {
        const int e = (tile0 + GRID_X) * TILE_M + (tid & 63);
        idx_sm[128 + tid] = (tid < 64) ? __ldg(src_idx + e) : __ldg(tgt_idx + e);
    }
    __syncthreads();   // A buf0 + idx(t0+G) ready

    // ======== pipelined main loop ========
    int p = 0, q = 0;
    for (int tile = tile0; tile < N_TILES; tile += GRID_X) {
        const int nxt = tile + GRID_X;
        int ntgt0 = 0, ntgt1 = 0;

        // ---- stage 1: gather(nxt) into A buf p^1 (overlaps MMA below) ----
        if (nxt < N_TILES) {
            const int* idxp = idx_sm + (q ^ 1) * 128;
            const uint32_t abase = (p ^ 1) ? SM_A1 : SM_A0;
            #pragma unroll
            for (int half = 0; half < 2; ++half) {
                const float* pp[6]; int rowv[6], segv[6];
                #pragma unroll
                for (int i = 0; i < 6; ++i) {
                    const int rs  = g_rs0 + (half * 6 + i) * 16;
                    const int row = rs & (TILE_M - 1);
                    const int seg = rs >> 6;
                    rowv[i] = row; segv[i] = seg;
                    pp[i] = (seg == 2)
                         ? edge_feat + (size_t)(nxt * TILE_M + row) * D_FEAT
                         : node_feat + (size_t)idxp[rs] * D_FEAT;
                }
                float4 v[6];
                #pragma unroll
                for (int i = 0; i < 6; ++i)
                    v[i] = __ldg(reinterpret_cast<const float4*>(pp[i]) + g_chunk);
                #pragma unroll
                for (int i = 0; i < 6; ++i) {
                    uint2 hh;
                    hh.x = pack_h2(v[i].x, v[i].y);
                    hh.y = pack_h2(v[i].z, v[i].w);
                    const uint32_t off =
                        (uint32_t)(rowv[i] * STRIDE_B + segv[i] * 128 + g_chunk * 8);
                    *reinterpret_cast<uint2*>(smem + abase + off) = hh;
                }
            }
            ntgt0 = idxp[64 + r0];
            ntgt1 = idxp[64 + r0 + 8];
            if (tid < 128 && nxt + GRID_X < N_TILES) {
                const int e = (nxt + GRID_X) * TILE_M + (tid & 63);
                idx_sm[q * 128 + tid] =
                    (tid < 64) ? __ldg(src_idx + e) : __ldg(tgt_idx + e);
            }
        }

        // ---- stage 2: MMA(tile) from A buf p; B from registers ----
        const uint32_t aBase = smem_base + (p ? SM_A1 : SM_A0);
        const uint32_t aK = aBase + aoffK;
        const uint32_t aG = aBase + aoffG;
        float accK[4][4], accG[4][4];
        #pragma unroll
        for (int j = 0; j < 4; ++j)
            #pragma unroll
            for (int qq = 0; qq < 4; ++qq) { accK[j][qq] = 0.f; accG[j][qq] = 0.f; }

        #pragma unroll
        for (int ks = 0; ks < 6; ++ks) {   // 6 k-steps (this warp's K half)
            const uint32_t kb = (uint32_t)(ks * 32);
            uint32_t ak[4], ag[4];
            ldsm_x4(ak, aK + kb);
            ldsm_x4(ag, aG + kb);
            #pragma unroll
            for (int nb = 0; nb < 4; ++nb) {
                mma_f16(accK[nb], ak, breg[ks][nb]);
                mma_f16(accG[nb], ag, breg[ks][nb]);
            }
        }

        // ---- exchange give-away block with kg partner ----
        #pragma unroll
        for (int nb = 0; nb < 4; ++nb)
            *reinterpret_cast<float4*>(myslot + nb * 16) =
                make_float4(accG[nb][0], accG[nb][1], accG[nb][2], accG[nb][3]);
        __syncthreads();   // partials visible (also: A buf p^1 & idx staged)

        // ---- combine + bias + relu + red.v2 scatter (16 rows per warp) ----
        {
            float* o0 = out + (size_t)tgtr0 * UNITS + ng * 32 + 2 * t4;
            float* o1 = out + (size_t)tgtr1 * UNITS + ng * 32 + 2 * t4;
            #pragma unroll
            for (int nb = 0; nb < 4; ++nb) {
                float4 pr = *reinterpret_cast<const float4*>(prslot + nb * 16);
                float v0 = fmaxf(accK[nb][0] + pr.x + bj0[nb], 0.f);
                float v1 = fmaxf(accK[nb][1] + pr.y + bj1[nb], 0.f);
                float v2 = fmaxf(accK[nb][2] + pr.z + bj0[nb], 0.f);
                float v3 = fmaxf(accK[nb][3] + pr.w + bj1[nb], 0.f);
                asm volatile("red.global.add.v2.f32 [%0], {%1, %2};"
                             :: "l"(o0 + nb * 8), "f"(v0), "f"(v1) : "memory");
                asm volatile("red.global.add.v2.f32 [%0], {%1, %2};"
                             :: "l"(o1 + nb * 8), "f"(v2), "f"(v3) : "memory");
            }
        }

        __syncthreads();   // partner read my slot; safe to reuse next iter
        tgtr0 = ntgt0; tgtr1 = ntgt1;
        p ^= 1; q ^= 1;
    }
}

// ---------------- launch ----------------

extern "C" void kernel_launch(void* const* d_in, const int* in_sizes, int n_in,
                              void* d_out, int out_size) {
    const float* node_feat = (const float*)d_in[0];
    const float* edge_feat = (const float*)d_in[1];
    const int*   src_idx   = (const int*)d_in[2];
    const int*   tgt_idx   = (const int*)d_in[3];
    const float* W         = (const float*)d_in[4];
    const float* b         = (const float*)d_in[5];
    float* out = (float*)d_out;

    int n4 = NN_NODES * UNITS / 4;
    zero_out_kernel<<<(n4 + 255) / 256, 256>>>((float4*)out);

    static int configured = 0;
    if (!configured) {
        cudaFuncSetAttribute(edgeconv_kernel,
                             cudaFuncAttributeMaxDynamicSharedMemorySize, SM_TOTAL);
        configured = 1;
    }
    edgeconv_kernel<<<GRID_X, THREADS, SM_TOTAL>>>(
        node_feat, edge_feat, src_idx, tgt_idx, W, b, out);
}